// round 5
// baseline (speedup 1.0000x reference)
#include <cuda_runtime.h>
#include <cuda_fp16.h>
#include <cstdint>

#define NL 1024
#define NB 32
#define NT 12
#define NF 4
#define NH 64

// Scratch (static device globals: allocation-free rule)
__device__ float g_h[2][NL * NH * NB];      // hidden, layout [L][H][B], double buffered
__device__ float g_xT[NT * NL * NF * NB];   // x transposed to [T][L][F][B]
__device__ float g_bias[4][NL * NH];        // [0]=b_rh+b_ri, [1]=b_uh+b_ui, [2]=b_nh, [3]=b_ni ; layout [L][H]
__device__ __half g_wh16[NL * NH * 3 * NH]; // hidden-gate weights fp16, packed [l][h][gate][k] (24 MB)

// packed f32x2 FMA: d = a*b + c (two independent fp32 lanes, full-rate on sm_10x)
__device__ __forceinline__ float2 ffma2(float2 a, float2 b, float2 c) {
    unsigned long long ua = *reinterpret_cast<unsigned long long*>(&a);
    unsigned long long ub = *reinterpret_cast<unsigned long long*>(&b);
    unsigned long long uc = *reinterpret_cast<unsigned long long*>(&c);
    unsigned long long ud;
    asm("fma.rn.f32x2 %0, %1, %2, %3;" : "=l"(ud) : "l"(ua), "l"(ub), "l"(uc));
    return *reinterpret_cast<float2*>(&ud);
}

__device__ __forceinline__ void cp16(uint32_t dst, const void* src) {
    asm volatile("cp.async.cg.shared.global [%0], [%1], 16;\n" :: "r"(dst), "l"(src));
}
__device__ __forceinline__ void cp_commit() {
    asm volatile("cp.async.commit_group;\n" ::: "memory");
}
template <int N>
__device__ __forceinline__ void cp_wait() {
    asm volatile("cp.async.wait_group %0;\n" :: "n"(N) : "memory");
}

__device__ __forceinline__ float fsigmoid(float x) {
    return __fdividef(1.0f, 1.0f + __expf(-x));
}
__device__ __forceinline__ float ftanh_fast(float x) {
    float e = __expf(2.0f * x);                 // inf for large x -> n = 1 (correct)
    return 1.0f - __fdividef(2.0f, e + 1.0f);   // e->0 -> -1 (correct)
}

// ---------------- prep kernels ----------------

__global__ void prep_bias(const float* __restrict__ b_rh, const float* __restrict__ b_ri,
                          const float* __restrict__ b_uh, const float* __restrict__ b_ui,
                          const float* __restrict__ b_nh, const float* __restrict__ b_ni) {
    int idx = blockIdx.x * blockDim.x + threadIdx.x;   // 4 * L * H = 262144
    if (idx >= 4 * NL * NH) return;
    int q = idx >> 16;           // which bias set
    int r = idx & 65535;         // l*64 + k
    int l = r >> 6;
    int k = r & 63;
    int src = k * NL + l;        // biases are [H][L]
    float v;
    if (q == 0)      v = b_rh[src] + b_ri[src];
    else if (q == 1) v = b_uh[src] + b_ui[src];
    else if (q == 2) v = b_nh[src];
    else             v = b_ni[src];
    g_bias[q][r] = v;
}

__global__ void prep_x(const float* __restrict__ x) {
    int idx = blockIdx.x * blockDim.x + threadIdx.x;   // T*L*F*B = 1572864
    if (idx >= NT * NL * NF * NB) return;
    int b = idx & 31;
    int f = (idx >> 5) & 3;
    int l = (idx >> 7) & 1023;
    int t = idx >> 17;
    g_xT[idx] = x[((b * NT + t) * NF + f) * NL + l];
}

// pack the three hidden-gate weight tensors [l][h][k] fp32 -> [l][h][gate][k] fp16
__global__ void prep_w16(const float* __restrict__ w_rh, const float* __restrict__ w_uh,
                         const float* __restrict__ w_nh) {
    int idx = blockIdx.x * blockDim.x + threadIdx.x;   // NL * NH * NH = 4194304
    if (idx >= NL * NH * NH) return;
    int l = idx >> 12;
    int hk = idx & 4095;          // h*64 + k
    int h = hk >> 6;
    int k = hk & 63;
    __half* dst = g_wh16 + ((l * NH + h) * 3) * NH + k;
    dst[0]       = __float2half(w_rh[idx]);
    dst[NH]      = __float2half(w_uh[idx]);
    dst[2 * NH]  = __float2half(w_nh[idx]);
}

// ---------------- GRU step kernel ----------------
// block = link l, 128 threads, 5 CTAs/SM. Thread tile: 4b x 4k x 3 gates (48 acc).
// Hidden weights are fp16 ([h][gate][k] rows of 384B), streamed via cp.async as
// 4 chunks of 16 h-rows (6KB each, 4 commit groups), consumed with progressive
// wait_group. fp16 halves smem return-bandwidth (the measured bottleneck):
// per row per warp delivered bytes = 3x256 (LDS.64 w) + 512 (LDS.128 hatt).
// smem: [0..2048) floats hatt [h][b]; bytes [8192..32768) fp16 weights.

template <bool FIRST>
__global__ void __launch_bounds__(128, 5)
step_kernel(const float* __restrict__ att,
            const float* __restrict__ w_ri, const float* __restrict__ w_ui, const float* __restrict__ w_ni,
            int t, int cur, int nxt) {
    extern __shared__ float smem[];
    float* sHatt = smem;                             // [64][32] fp32
    char*  sW16  = (char*)smem + 8192;               // [64][3][64] fp16 (24KB)

    const int l   = blockIdx.x;
    const int tid = threadIdx.x;
    const int k0 = (tid & 15) * 4;
    const int b0 = (tid >> 4) * 4;

    if (!FIRST) {
        // ---- stream all hidden weights: 4 chunks x 6KB, one commit group each ----
        uint32_t dstb = (uint32_t)__cvta_generic_to_shared(sW16);
        const char* srcb = (const char*)(g_wh16 + l * (NH * 3 * NH));
#pragma unroll
        for (int c = 0; c < 4; c++) {
            int base = c * 6144;
            cp16(dstb + base + tid * 16,        srcb + base + tid * 16);
            cp16(dstb + base + 2048 + tid * 16, srcb + base + 2048 + tid * 16);
            cp16(dstb + base + 4096 + tid * 16, srcb + base + 4096 + tid * 16);
            cp_commit();
        }

        // ---- graph attention under the copy latency ----
        float a0 = att[l * NL + l];
        float am = (l > 0)      ? att[l * NL + l - 1] : 0.0f;
        float ap = (l < NL - 1) ? att[l * NL + l + 1] : 0.0f;
        const int lm = (l > 0) ? l - 1 : l;
        const int lp = (l < NL - 1) ? l + 1 : l;
        const float4* hm = (const float4*)(g_h[cur] + lm * (NH * NB));
        const float4* hc = (const float4*)(g_h[cur] + l  * (NH * NB));
        const float4* hp = (const float4*)(g_h[cur] + lp * (NH * NB));
        float4* sh = (float4*)sHatt;
#pragma unroll
        for (int i = 0; i < 4; i++) {
            int j = tid + i * 128;
            float4 m = hm[j], c4 = hc[j], p = hp[j];
            float4 v;
            v.x = am * m.x + a0 * c4.x + ap * p.x;
            v.y = am * m.y + a0 * c4.y + ap * p.y;
            v.z = am * m.z + a0 * c4.z + ap * p.z;
            v.w = am * m.w + a0 * c4.w + ap * p.w;
            sh[j] = v;
        }
    }

    // --- accumulators: init from combined biases (x-part added in epilogue) ---
    float2 aR2[8], aZ2[8], aN2[8];
    float* accR  = (float*)aR2;
    float* accZ  = (float*)aZ2;
    float* accNH = (float*)aN2;
    {
        float4 br = *(const float4*)&g_bias[0][l * 64 + k0];
        float4 bz = *(const float4*)&g_bias[1][l * 64 + k0];
        float4 bh = *(const float4*)&g_bias[2][l * 64 + k0];
#pragma unroll
        for (int bb = 0; bb < 4; bb++) {
            aR2[bb * 2 + 0] = make_float2(br.x, br.y);  aR2[bb * 2 + 1] = make_float2(br.z, br.w);
            aZ2[bb * 2 + 0] = make_float2(bz.x, bz.y);  aZ2[bb * 2 + 1] = make_float2(bz.z, bz.w);
            aN2[bb * 2 + 0] = make_float2(bh.x, bh.y);  aN2[bb * 2 + 1] = make_float2(bh.z, bh.w);
        }
    }

    if (!FIRST) {
        auto gemm_chunk = [&](int hbase) {
#pragma unroll
            for (int hh = 0; hh < 16; hh++) {
                const int hr = hbase + hh;
                float4 hv = *(const float4*)&sHatt[hr * 32 + b0];
                float2 hb[4] = { {hv.x, hv.x}, {hv.y, hv.y}, {hv.z, hv.z}, {hv.w, hv.w} };
                const char* row = sW16 + hr * 384 + k0 * 2;
                __half2 r16a = *(const __half2*)(row + 0);
                __half2 r16b = *(const __half2*)(row + 4);
                __half2 u16a = *(const __half2*)(row + 128);
                __half2 u16b = *(const __half2*)(row + 132);
                __half2 n16a = *(const __half2*)(row + 256);
                __half2 n16b = *(const __half2*)(row + 260);
                float2 wr0 = __half22float2(r16a), wr1 = __half22float2(r16b);
                float2 wu0 = __half22float2(u16a), wu1 = __half22float2(u16b);
                float2 wn0 = __half22float2(n16a), wn1 = __half22float2(n16b);
#pragma unroll
                for (int bb = 0; bb < 4; bb++) {
                    aR2[bb * 2 + 0] = ffma2(hb[bb], wr0, aR2[bb * 2 + 0]);
                    aR2[bb * 2 + 1] = ffma2(hb[bb], wr1, aR2[bb * 2 + 1]);
                    aZ2[bb * 2 + 0] = ffma2(hb[bb], wu0, aZ2[bb * 2 + 0]);
                    aZ2[bb * 2 + 1] = ffma2(hb[bb], wu1, aZ2[bb * 2 + 1]);
                    aN2[bb * 2 + 0] = ffma2(hb[bb], wn0, aN2[bb * 2 + 0]);
                    aN2[bb * 2 + 1] = ffma2(hb[bb], wn1, aN2[bb * 2 + 1]);
                }
            }
        };

        cp_wait<3>(); __syncthreads();   // chunk 0 + hatt visible
        gemm_chunk(0);
        cp_wait<2>(); __syncthreads();
        gemm_chunk(16);
        cp_wait<1>(); __syncthreads();
        gemm_chunk(32);
        cp_wait<0>(); __syncthreads();
        gemm_chunk(48);
    }

    // --- epilogue: x-GEMM (F=4, fp32) + b_ni, then gates + write h_next ---
    float2 xiN2[8];
    float* xiN = (float*)xiN2;
    {
        float4 bn = *(const float4*)&g_bias[3][l * 64 + k0];
#pragma unroll
        for (int bb = 0; bb < 4; bb++) {
            xiN2[bb * 2 + 0] = make_float2(bn.x, bn.y);
            xiN2[bb * 2 + 1] = make_float2(bn.z, bn.w);
        }
        const float* xb = g_xT + (t * NL + l) * (NF * NB);
#pragma unroll
        for (int f = 0; f < 4; f++) {
            float4 xv = *(const float4*)&xb[f * 32 + b0];
            float2 xs[4] = { {xv.x, xv.x}, {xv.y, xv.y}, {xv.z, xv.z}, {xv.w, xv.w} };
            float4 wr = *(const float4*)&w_ri[l * 256 + f * 64 + k0];
            float4 wu = *(const float4*)&w_ui[l * 256 + f * 64 + k0];
            float4 wn = *(const float4*)&w_ni[l * 256 + f * 64 + k0];
            float2 wr0 = make_float2(wr.x, wr.y), wr1 = make_float2(wr.z, wr.w);
            float2 wu0 = make_float2(wu.x, wu.y), wu1 = make_float2(wu.z, wu.w);
            float2 wn0 = make_float2(wn.x, wn.y), wn1 = make_float2(wn.z, wn.w);
#pragma unroll
            for (int bb = 0; bb < 4; bb++) {
                aR2[bb * 2 + 0] = ffma2(xs[bb], wr0, aR2[bb * 2 + 0]);
                aR2[bb * 2 + 1] = ffma2(xs[bb], wr1, aR2[bb * 2 + 1]);
                aZ2[bb * 2 + 0] = ffma2(xs[bb], wu0, aZ2[bb * 2 + 0]);
                aZ2[bb * 2 + 1] = ffma2(xs[bb], wu1, aZ2[bb * 2 + 1]);
                xiN2[bb * 2 + 0] = ffma2(xs[bb], wn0, xiN2[bb * 2 + 0]);
                xiN2[bb * 2 + 1] = ffma2(xs[bb], wn1, xiN2[bb * 2 + 1]);
            }
        }
    }

    const float* hcur = g_h[cur] + l * (NH * NB);
    float* hnxt = g_h[nxt] + l * (NH * NB);
#pragma unroll
    for (int kk = 0; kk < 4; kk++) {
        int k = k0 + kk;
        float holdv[4] = {0.f, 0.f, 0.f, 0.f};
        if (!FIRST) {
            float4 h4 = *(const float4*)&hcur[k * 32 + b0];
            holdv[0] = h4.x; holdv[1] = h4.y; holdv[2] = h4.z; holdv[3] = h4.w;
        }
        float o[4];
#pragma unroll
        for (int bb = 0; bb < 4; bb++) {
            int p = bb * 4 + kk;
            float r = fsigmoid(accR[p]);
            float z = fsigmoid(accZ[p]);
            float n = ftanh_fast(xiN[p] + r * accNH[p]);
            o[bb] = n + z * (holdv[bb] - n);
        }
        *(float4*)&hnxt[k * 32 + b0] = make_float4(o[0], o[1], o[2], o[3]);
    }
}

// ---------------- output head ----------------
__global__ void fc_kernel(const float* __restrict__ w_fc, const float* __restrict__ b_fc,
                          float* __restrict__ out) {
    int l = blockIdx.x;
    int b = threadIdx.x;   // 32 threads
    const float* h = g_h[0] + l * (NH * NB);
    float acc = b_fc[l];
#pragma unroll 8
    for (int k = 0; k < NH; k++) acc += h[k * 32 + b] * w_fc[l * NH + k];
    out[b * NL + l] = acc;   // [B][O=1][L]
}

// ---------------- launch ----------------
#define STEP_SMEM (8192 + 24576)   // 8KB hatt + 24KB fp16 weights = 32KB (<=48KB default)

extern "C" void kernel_launch(void* const* d_in, const int* in_sizes, int n_in,
                              void* d_out, int out_size) {
    const float* x    = (const float*)d_in[0];
    const float* att  = (const float*)d_in[1];
    const float* w_rh = (const float*)d_in[2];
    const float* b_rh = (const float*)d_in[3];
    const float* w_ri = (const float*)d_in[4];
    const float* b_ri = (const float*)d_in[5];
    const float* w_uh = (const float*)d_in[6];
    const float* b_uh = (const float*)d_in[7];
    const float* w_ui = (const float*)d_in[8];
    const float* b_ui = (const float*)d_in[9];
    const float* w_nh = (const float*)d_in[10];
    const float* b_nh = (const float*)d_in[11];
    const float* w_ni = (const float*)d_in[12];
    const float* b_ni = (const float*)d_in[13];
    const float* w_fc = (const float*)d_in[14];
    const float* b_fc = (const float*)d_in[15];

    prep_bias<<<1024, 256>>>(b_rh, b_ri, b_uh, b_ui, b_nh, b_ni);
    prep_x<<<6144, 256>>>(x);
    prep_w16<<<16384, 256>>>(w_rh, w_uh, w_nh);

    // t=0: h=0, skip attention + hidden GEMM
    step_kernel<true><<<1024, 128, STEP_SMEM>>>(att, w_ri, w_ui, w_ni, 0, 0, 1);
    for (int t = 1; t < NT; t++) {
        step_kernel<false><<<1024, 128, STEP_SMEM>>>(att, w_ri, w_ui, w_ni,
                                                     t, t & 1, (t + 1) & 1);
    }
    // after t=11 (writes buffer 0)
    fc_kernel<<<1024, 32>>>(w_fc, b_fc, (float*)d_out);
}

// round 7
// speedup vs baseline: 1.0001x; 1.0001x over previous
#include <cuda_runtime.h>
#include <cuda_fp16.h>
#include <cstdint>

#define NL 1024
#define NB 32
#define NT 12
#define NF 4
#define NH 64

// Scratch (static device globals: allocation-free rule)
__device__ float g_h[2][NL * NH * NB];      // hidden, layout [L][H][B], double buffered
__device__ float g_xT[NT * NL * NF * NB];   // x transposed to [T][L][F][B]
__device__ float g_bias[4][NL * NH];        // [0]=b_rh+b_ri, [1]=b_uh+b_ui, [2]=b_nh, [3]=b_ni ; layout [L][H]
__device__ __half g_wh16[NL * NH * 3 * NH]; // hidden-gate weights fp16, packed [l][h][gate][k] (24 MB)

// packed f32x2 FMA: d = a*b + c (two independent fp32 lanes, full-rate on sm_10x)
__device__ __forceinline__ float2 ffma2(float2 a, float2 b, float2 c) {
    unsigned long long ua = *reinterpret_cast<unsigned long long*>(&a);
    unsigned long long ub = *reinterpret_cast<unsigned long long*>(&b);
    unsigned long long uc = *reinterpret_cast<unsigned long long*>(&c);
    unsigned long long ud;
    asm("fma.rn.f32x2 %0, %1, %2, %3;" : "=l"(ud) : "l"(ua), "l"(ub), "l"(uc));
    return *reinterpret_cast<float2*>(&ud);
}

__device__ __forceinline__ void cp16(uint32_t dst, const void* src) {
    asm volatile("cp.async.cg.shared.global [%0], [%1], 16;\n" :: "r"(dst), "l"(src));
}
__device__ __forceinline__ void cp_commit() {
    asm volatile("cp.async.commit_group;\n" ::: "memory");
}
template <int N>
__device__ __forceinline__ void cp_wait() {
    asm volatile("cp.async.wait_group %0;\n" :: "n"(N) : "memory");
}

__device__ __forceinline__ float fsigmoid(float x) {
    return __fdividef(1.0f, 1.0f + __expf(-x));
}
__device__ __forceinline__ float ftanh_fast(float x) {
    float e = __expf(2.0f * x);                 // inf for large x -> n = 1 (correct)
    return 1.0f - __fdividef(2.0f, e + 1.0f);   // e->0 -> -1 (correct)
}

// ---------------- prep kernels ----------------

__global__ void prep_bias(const float* __restrict__ b_rh, const float* __restrict__ b_ri,
                          const float* __restrict__ b_uh, const float* __restrict__ b_ui,
                          const float* __restrict__ b_nh, const float* __restrict__ b_ni) {
    int idx = blockIdx.x * blockDim.x + threadIdx.x;   // 4 * L * H = 262144
    if (idx >= 4 * NL * NH) return;
    int q = idx >> 16;           // which bias set
    int r = idx & 65535;         // l*64 + k
    int l = r >> 6;
    int k = r & 63;
    int src = k * NL + l;        // biases are [H][L]
    float v;
    if (q == 0)      v = b_rh[src] + b_ri[src];
    else if (q == 1) v = b_uh[src] + b_ui[src];
    else if (q == 2) v = b_nh[src];
    else             v = b_ni[src];
    g_bias[q][r] = v;
}

__global__ void prep_x(const float* __restrict__ x) {
    int idx = blockIdx.x * blockDim.x + threadIdx.x;   // T*L*F*B = 1572864
    if (idx >= NT * NL * NF * NB) return;
    int b = idx & 31;
    int f = (idx >> 5) & 3;
    int l = (idx >> 7) & 1023;
    int t = idx >> 17;
    g_xT[idx] = x[((b * NT + t) * NF + f) * NL + l];
}

// pack the three hidden-gate weight tensors [l][h][k] fp32 -> [l][h][gate][k] fp16
__global__ void prep_w16(const float* __restrict__ w_rh, const float* __restrict__ w_uh,
                         const float* __restrict__ w_nh) {
    int idx = blockIdx.x * blockDim.x + threadIdx.x;   // NL * NH * NH = 4194304
    if (idx >= NL * NH * NH) return;
    int l = idx >> 12;
    int hk = idx & 4095;          // h*64 + k
    int h = hk >> 6;
    int k = hk & 63;
    __half* dst = g_wh16 + ((l * NH + h) * 3) * NH + k;
    dst[0]       = __float2half(w_rh[idx]);
    dst[NH]      = __float2half(w_uh[idx]);
    dst[2 * NH]  = __float2half(w_nh[idx]);
}

// ---------------- GRU step kernel ----------------
// block = link l, 128 threads, 5 CTAs/SM. Thread tile: 4b x 4k x 3 gates (48 acc).
// Hidden weights are fp16 ([h][gate][k] rows of 384B), streamed via cp.async as
// 4 chunks of 16 h-rows (6KB each, 4 commit groups), consumed with progressive
// wait_group. fp16 halves smem return-bandwidth (the measured bottleneck):
// per row per warp delivered bytes = 3x256 (LDS.64 w) + 512 (LDS.128 hatt).
// smem: [0..2048) floats hatt [h][b]; bytes [8192..32768) fp16 weights.

template <bool FIRST>
__global__ void __launch_bounds__(128, 5)
step_kernel(const float* __restrict__ att,
            const float* __restrict__ w_ri, const float* __restrict__ w_ui, const float* __restrict__ w_ni,
            int t, int cur, int nxt) {
    extern __shared__ float smem[];
    float* sHatt = smem;                             // [64][32] fp32
    char*  sW16  = (char*)smem + 8192;               // [64][3][64] fp16 (24KB)

    const int l   = blockIdx.x;
    const int tid = threadIdx.x;
    const int k0 = (tid & 15) * 4;
    const int b0 = (tid >> 4) * 4;

    if (!FIRST) {
        // ---- stream all hidden weights: 4 chunks x 6KB, one commit group each ----
        uint32_t dstb = (uint32_t)__cvta_generic_to_shared(sW16);
        const char* srcb = (const char*)(g_wh16 + l * (NH * 3 * NH));
#pragma unroll
        for (int c = 0; c < 4; c++) {
            int base = c * 6144;
            cp16(dstb + base + tid * 16,        srcb + base + tid * 16);
            cp16(dstb + base + 2048 + tid * 16, srcb + base + 2048 + tid * 16);
            cp16(dstb + base + 4096 + tid * 16, srcb + base + 4096 + tid * 16);
            cp_commit();
        }

        // ---- graph attention under the copy latency ----
        float a0 = att[l * NL + l];
        float am = (l > 0)      ? att[l * NL + l - 1] : 0.0f;
        float ap = (l < NL - 1) ? att[l * NL + l + 1] : 0.0f;
        const int lm = (l > 0) ? l - 1 : l;
        const int lp = (l < NL - 1) ? l + 1 : l;
        const float4* hm = (const float4*)(g_h[cur] + lm * (NH * NB));
        const float4* hc = (const float4*)(g_h[cur] + l  * (NH * NB));
        const float4* hp = (const float4*)(g_h[cur] + lp * (NH * NB));
        float4* sh = (float4*)sHatt;
#pragma unroll
        for (int i = 0; i < 4; i++) {
            int j = tid + i * 128;
            float4 m = hm[j], c4 = hc[j], p = hp[j];
            float4 v;
            v.x = am * m.x + a0 * c4.x + ap * p.x;
            v.y = am * m.y + a0 * c4.y + ap * p.y;
            v.z = am * m.z + a0 * c4.z + ap * p.z;
            v.w = am * m.w + a0 * c4.w + ap * p.w;
            sh[j] = v;
        }
    }

    // --- accumulators: init from combined biases (x-part added in epilogue) ---
    float2 aR2[8], aZ2[8], aN2[8];
    float* accR  = (float*)aR2;
    float* accZ  = (float*)aZ2;
    float* accNH = (float*)aN2;
    {
        float4 br = *(const float4*)&g_bias[0][l * 64 + k0];
        float4 bz = *(const float4*)&g_bias[1][l * 64 + k0];
        float4 bh = *(const float4*)&g_bias[2][l * 64 + k0];
#pragma unroll
        for (int bb = 0; bb < 4; bb++) {
            aR2[bb * 2 + 0] = make_float2(br.x, br.y);  aR2[bb * 2 + 1] = make_float2(br.z, br.w);
            aZ2[bb * 2 + 0] = make_float2(bz.x, bz.y);  aZ2[bb * 2 + 1] = make_float2(bz.z, bz.w);
            aN2[bb * 2 + 0] = make_float2(bh.x, bh.y);  aN2[bb * 2 + 1] = make_float2(bh.z, bh.w);
        }
    }

    if (!FIRST) {
        auto gemm_chunk = [&](int hbase) {
#pragma unroll
            for (int hh = 0; hh < 16; hh++) {
                const int hr = hbase + hh;
                float4 hv = *(const float4*)&sHatt[hr * 32 + b0];
                float2 hb[4] = { {hv.x, hv.x}, {hv.y, hv.y}, {hv.z, hv.z}, {hv.w, hv.w} };
                const char* row = sW16 + hr * 384 + k0 * 2;
                __half2 r16a = *(const __half2*)(row + 0);
                __half2 r16b = *(const __half2*)(row + 4);
                __half2 u16a = *(const __half2*)(row + 128);
                __half2 u16b = *(const __half2*)(row + 132);
                __half2 n16a = *(const __half2*)(row + 256);
                __half2 n16b = *(const __half2*)(row + 260);
                float2 wr0 = __half22float2(r16a), wr1 = __half22float2(r16b);
                float2 wu0 = __half22float2(u16a), wu1 = __half22float2(u16b);
                float2 wn0 = __half22float2(n16a), wn1 = __half22float2(n16b);
#pragma unroll
                for (int bb = 0; bb < 4; bb++) {
                    aR2[bb * 2 + 0] = ffma2(hb[bb], wr0, aR2[bb * 2 + 0]);
                    aR2[bb * 2 + 1] = ffma2(hb[bb], wr1, aR2[bb * 2 + 1]);
                    aZ2[bb * 2 + 0] = ffma2(hb[bb], wu0, aZ2[bb * 2 + 0]);
                    aZ2[bb * 2 + 1] = ffma2(hb[bb], wu1, aZ2[bb * 2 + 1]);
                    aN2[bb * 2 + 0] = ffma2(hb[bb], wn0, aN2[bb * 2 + 0]);
                    aN2[bb * 2 + 1] = ffma2(hb[bb], wn1, aN2[bb * 2 + 1]);
                }
            }
        };

        cp_wait<3>(); __syncthreads();   // chunk 0 + hatt visible
        gemm_chunk(0);
        cp_wait<2>(); __syncthreads();
        gemm_chunk(16);
        cp_wait<1>(); __syncthreads();
        gemm_chunk(32);
        cp_wait<0>(); __syncthreads();
        gemm_chunk(48);
    }

    // --- epilogue: x-GEMM (F=4, fp32) + b_ni, then gates + write h_next ---
    float2 xiN2[8];
    float* xiN = (float*)xiN2;
    {
        float4 bn = *(const float4*)&g_bias[3][l * 64 + k0];
#pragma unroll
        for (int bb = 0; bb < 4; bb++) {
            xiN2[bb * 2 + 0] = make_float2(bn.x, bn.y);
            xiN2[bb * 2 + 1] = make_float2(bn.z, bn.w);
        }
        const float* xb = g_xT + (t * NL + l) * (NF * NB);
#pragma unroll
        for (int f = 0; f < 4; f++) {
            float4 xv = *(const float4*)&xb[f * 32 + b0];
            float2 xs[4] = { {xv.x, xv.x}, {xv.y, xv.y}, {xv.z, xv.z}, {xv.w, xv.w} };
            float4 wr = *(const float4*)&w_ri[l * 256 + f * 64 + k0];
            float4 wu = *(const float4*)&w_ui[l * 256 + f * 64 + k0];
            float4 wn = *(const float4*)&w_ni[l * 256 + f * 64 + k0];
            float2 wr0 = make_float2(wr.x, wr.y), wr1 = make_float2(wr.z, wr.w);
            float2 wu0 = make_float2(wu.x, wu.y), wu1 = make_float2(wu.z, wu.w);
            float2 wn0 = make_float2(wn.x, wn.y), wn1 = make_float2(wn.z, wn.w);
#pragma unroll
            for (int bb = 0; bb < 4; bb++) {
                aR2[bb * 2 + 0] = ffma2(xs[bb], wr0, aR2[bb * 2 + 0]);
                aR2[bb * 2 + 1] = ffma2(xs[bb], wr1, aR2[bb * 2 + 1]);
                aZ2[bb * 2 + 0] = ffma2(xs[bb], wu0, aZ2[bb * 2 + 0]);
                aZ2[bb * 2 + 1] = ffma2(xs[bb], wu1, aZ2[bb * 2 + 1]);
                xiN2[bb * 2 + 0] = ffma2(xs[bb], wn0, xiN2[bb * 2 + 0]);
                xiN2[bb * 2 + 1] = ffma2(xs[bb], wn1, xiN2[bb * 2 + 1]);
            }
        }
    }

    const float* hcur = g_h[cur] + l * (NH * NB);
    float* hnxt = g_h[nxt] + l * (NH * NB);
#pragma unroll
    for (int kk = 0; kk < 4; kk++) {
        int k = k0 + kk;
        float holdv[4] = {0.f, 0.f, 0.f, 0.f};
        if (!FIRST) {
            float4 h4 = *(const float4*)&hcur[k * 32 + b0];
            holdv[0] = h4.x; holdv[1] = h4.y; holdv[2] = h4.z; holdv[3] = h4.w;
        }
        float o[4];
#pragma unroll
        for (int bb = 0; bb < 4; bb++) {
            int p = bb * 4 + kk;
            float r = fsigmoid(accR[p]);
            float z = fsigmoid(accZ[p]);
            float n = ftanh_fast(xiN[p] + r * accNH[p]);
            o[bb] = n + z * (holdv[bb] - n);
        }
        *(float4*)&hnxt[k * 32 + b0] = make_float4(o[0], o[1], o[2], o[3]);
    }
}

// ---------------- output head ----------------
__global__ void fc_kernel(const float* __restrict__ w_fc, const float* __restrict__ b_fc,
                          float* __restrict__ out) {
    int l = blockIdx.x;
    int b = threadIdx.x;   // 32 threads
    const float* h = g_h[0] + l * (NH * NB);
    float acc = b_fc[l];
#pragma unroll 8
    for (int k = 0; k < NH; k++) acc += h[k * 32 + b] * w_fc[l * NH + k];
    out[b * NL + l] = acc;   // [B][O=1][L]
}

// ---------------- launch ----------------
#define STEP_SMEM (8192 + 24576)   // 8KB hatt + 24KB fp16 weights = 32KB (<=48KB default)

extern "C" void kernel_launch(void* const* d_in, const int* in_sizes, int n_in,
                              void* d_out, int out_size) {
    const float* x    = (const float*)d_in[0];
    const float* att  = (const float*)d_in[1];
    const float* w_rh = (const float*)d_in[2];
    const float* b_rh = (const float*)d_in[3];
    const float* w_ri = (const float*)d_in[4];
    const float* b_ri = (const float*)d_in[5];
    const float* w_uh = (const float*)d_in[6];
    const float* b_uh = (const float*)d_in[7];
    const float* w_ui = (const float*)d_in[8];
    const float* b_ui = (const float*)d_in[9];
    const float* w_nh = (const float*)d_in[10];
    const float* b_nh = (const float*)d_in[11];
    const float* w_ni = (const float*)d_in[12];
    const float* b_ni = (const float*)d_in[13];
    const float* w_fc = (const float*)d_in[14];
    const float* b_fc = (const float*)d_in[15];

    prep_bias<<<1024, 256>>>(b_rh, b_ri, b_uh, b_ui, b_nh, b_ni);
    prep_x<<<6144, 256>>>(x);
    prep_w16<<<16384, 256>>>(w_rh, w_uh, w_nh);

    // t=0: h=0, skip attention + hidden GEMM
    step_kernel<true><<<1024, 128, STEP_SMEM>>>(att, w_ri, w_ui, w_ni, 0, 0, 1);
    for (int t = 1; t < NT; t++) {
        step_kernel<false><<<1024, 128, STEP_SMEM>>>(att, w_ri, w_ui, w_ni,
                                                     t, t & 1, (t + 1) & 1);
    }
    // after t=11 (writes buffer 0)
    fc_kernel<<<1024, 32>>>(w_fc, b_fc, (float*)d_out);
}

// round 8
// speedup vs baseline: 1.3595x; 1.3594x over previous
#include <cuda_runtime.h>
#include <cstdint>

#define NL 1024
#define NB 32
#define NT 12
#define NF 4
#define NH 64

// Scratch (static device globals: allocation-free rule)
__device__ float g_h[2][NL * NH * NB];      // hidden, layout [L][H][B], double buffered
__device__ float g_xT[NT * NL * NF * NB];   // x transposed to [T][L][F][B]
__device__ float g_bias[4][NL * NH];        // [0]=b_rh+b_ri, [1]=b_uh+b_ui, [2]=b_nh, [3]=b_ni ; layout [L][H]

// packed f32x2 FMA: d = a*b + c (two independent fp32 lanes, full-rate on sm_10x)
__device__ __forceinline__ float2 ffma2(float2 a, float2 b, float2 c) {
    unsigned long long ua = *reinterpret_cast<unsigned long long*>(&a);
    unsigned long long ub = *reinterpret_cast<unsigned long long*>(&b);
    unsigned long long uc = *reinterpret_cast<unsigned long long*>(&c);
    unsigned long long ud;
    asm("fma.rn.f32x2 %0, %1, %2, %3;" : "=l"(ud) : "l"(ua), "l"(ub), "l"(uc));
    return *reinterpret_cast<float2*>(&ud);
}

__device__ __forceinline__ void cp16(uint32_t dst, const void* src) {
    asm volatile("cp.async.cg.shared.global [%0], [%1], 16;\n" :: "r"(dst), "l"(src));
}
__device__ __forceinline__ void cp_commit() {
    asm volatile("cp.async.commit_group;\n" ::: "memory");
}
template <int N>
__device__ __forceinline__ void cp_wait() {
    asm volatile("cp.async.wait_group %0;\n" :: "n"(N) : "memory");
}

__device__ __forceinline__ float fsigmoid(float x) {
    return __fdividef(1.0f, 1.0f + __expf(-x));
}
__device__ __forceinline__ float ftanh_fast(float x) {
    float e = __expf(2.0f * x);                 // inf for large x -> n = 1 (correct)
    return 1.0f - __fdividef(2.0f, e + 1.0f);   // e->0 -> -1 (correct)
}

// ---------------- prep kernels ----------------

__global__ void prep_bias(const float* __restrict__ b_rh, const float* __restrict__ b_ri,
                          const float* __restrict__ b_uh, const float* __restrict__ b_ui,
                          const float* __restrict__ b_nh, const float* __restrict__ b_ni) {
    int idx = blockIdx.x * blockDim.x + threadIdx.x;   // 4 * L * H = 262144
    if (idx >= 4 * NL * NH) return;
    int q = idx >> 16;           // which bias set
    int r = idx & 65535;         // l*64 + k
    int l = r >> 6;
    int k = r & 63;
    int src = k * NL + l;        // biases are [H][L]
    float v;
    if (q == 0)      v = b_rh[src] + b_ri[src];
    else if (q == 1) v = b_uh[src] + b_ui[src];
    else if (q == 2) v = b_nh[src];
    else             v = b_ni[src];
    g_bias[q][r] = v;
}

__global__ void prep_x(const float* __restrict__ x) {
    int idx = blockIdx.x * blockDim.x + threadIdx.x;   // T*L*F*B = 1572864
    if (idx >= NT * NL * NF * NB) return;
    int b = idx & 31;
    int f = (idx >> 5) & 3;
    int l = (idx >> 7) & 1023;
    int t = idx >> 17;
    g_xT[idx] = x[((b * NT + t) * NF + f) * NL + l];
}

// ---------------- GRU step kernel ----------------
// block = link l, 128 threads, 4 CTAs/SM. Warp-autonomous k-slicing:
// warp w owns k in [w*16, w*16+16). Lane = kg*8+bg: kg=lane>>3 (4 k-subgroups),
// bg=lane&7 (8 b-groups). Thread tile 4b x 4k x 3 gates (48 fp32 acc).
// Each warp cp.asyncs ONLY the weight columns it consumes (12KB, 2 chunks of 32
// h-rows), then waits on its own cp groups + __syncwarp — no block barriers in
// the GEMM. The single __syncthreads protects the shared hatt tile.
// smem floats: [0..12288) weights, per-warp 3072: [row][gate][16k];
//              [12288..14336) hatt [h][b].

template <bool FIRST>
__global__ void __launch_bounds__(128, 4)
step_kernel(const float* __restrict__ att,
            const float* __restrict__ w_rh, const float* __restrict__ w_uh, const float* __restrict__ w_nh,
            const float* __restrict__ w_ri, const float* __restrict__ w_ui, const float* __restrict__ w_ni,
            int t, int cur, int nxt) {
    extern __shared__ float smem[];
    float* sHatt = smem + 12288;

    const int l    = blockIdx.x;
    const int tid  = threadIdx.x;
    const int lane = tid & 31;
    const int warp = tid >> 5;
    const int kg   = lane >> 3;         // 0..3
    const int bg   = lane & 7;          // 0..7
    const int k0   = warp * 16 + kg * 4;
    const int b0   = bg * 4;
    float* sWw = smem + warp * 3072;    // this warp's weight slice [64][3][16]

    if (!FIRST) {
        // ---- each warp streams its own 12KB weight slice: 2 chunks x 32 rows ----
        uint32_t dstb = (uint32_t)__cvta_generic_to_shared(sWw);
        const float* gsrc[3] = { w_rh + l * 4096 + warp * 16,
                                 w_uh + l * 4096 + warp * 16,
                                 w_nh + l * 4096 + warp * 16 };
#pragma unroll
        for (int c = 0; c < 2; c++) {
#pragma unroll
            for (int g = 0; g < 3; g++) {
#pragma unroll
                for (int i = 0; i < 4; i++) {
                    int idx = lane + i * 32;          // 0..127
                    int r   = idx >> 2;               // 0..31
                    int cc  = idx & 3;                // 16B chunk within 64B
                    cp16(dstb + (uint32_t)(((c * 32 + r) * 48 + g * 16 + cc * 4) * 4),
                         gsrc[g] + (c * 32 + r) * 64 + cc * 4);
                }
            }
            cp_commit();
        }

        // ---- graph attention (shared across warps) under the copy latency ----
        float a0 = att[l * NL + l];
        float am = (l > 0)      ? att[l * NL + l - 1] : 0.0f;
        float ap = (l < NL - 1) ? att[l * NL + l + 1] : 0.0f;
        const int lm = (l > 0) ? l - 1 : l;
        const int lp = (l < NL - 1) ? l + 1 : l;
        const float4* hm = (const float4*)(g_h[cur] + lm * (NH * NB));
        const float4* hc = (const float4*)(g_h[cur] + l  * (NH * NB));
        const float4* hp = (const float4*)(g_h[cur] + lp * (NH * NB));
        float4* sh = (float4*)sHatt;
#pragma unroll
        for (int i = 0; i < 4; i++) {
            int j = tid + i * 128;
            float4 m = hm[j], c4 = hc[j], p = hp[j];
            float4 v;
            v.x = am * m.x + a0 * c4.x + ap * p.x;
            v.y = am * m.y + a0 * c4.y + ap * p.y;
            v.z = am * m.z + a0 * c4.z + ap * p.z;
            v.w = am * m.w + a0 * c4.w + ap * p.w;
            sh[j] = v;
        }
    }

    // --- accumulators: init from combined biases (x-part added in epilogue) ---
    float2 aR2[8], aZ2[8], aN2[8];
    float* accR  = (float*)aR2;
    float* accZ  = (float*)aZ2;
    float* accNH = (float*)aN2;
    {
        float4 br = *(const float4*)&g_bias[0][l * 64 + k0];
        float4 bz = *(const float4*)&g_bias[1][l * 64 + k0];
        float4 bh = *(const float4*)&g_bias[2][l * 64 + k0];
#pragma unroll
        for (int bb = 0; bb < 4; bb++) {
            aR2[bb * 2 + 0] = make_float2(br.x, br.y);  aR2[bb * 2 + 1] = make_float2(br.z, br.w);
            aZ2[bb * 2 + 0] = make_float2(bz.x, bz.y);  aZ2[bb * 2 + 1] = make_float2(bz.z, bz.w);
            aN2[bb * 2 + 0] = make_float2(bh.x, bh.y);  aN2[bb * 2 + 1] = make_float2(bh.z, bh.w);
        }
    }

    if (!FIRST) {
        __syncthreads();   // hatt visible to all warps (the ONLY block barrier)

        auto gemm_chunk = [&](int hbase) {
#pragma unroll
            for (int hh = 0; hh < 32; hh++) {
                const int hr = hbase + hh;
                float4 hv = *(const float4*)&sHatt[hr * 32 + b0];
                float2 hb[4] = { {hv.x, hv.x}, {hv.y, hv.y}, {hv.z, hv.z}, {hv.w, hv.w} };
                const float* row = sWw + hr * 48 + kg * 4;
                float4 wr = *(const float4*)(row);
                float4 wu = *(const float4*)(row + 16);
                float4 wn = *(const float4*)(row + 32);
                float2 wr0 = make_float2(wr.x, wr.y), wr1 = make_float2(wr.z, wr.w);
                float2 wu0 = make_float2(wu.x, wu.y), wu1 = make_float2(wu.z, wu.w);
                float2 wn0 = make_float2(wn.x, wn.y), wn1 = make_float2(wn.z, wn.w);
#pragma unroll
                for (int bb = 0; bb < 4; bb++) {
                    aR2[bb * 2 + 0] = ffma2(hb[bb], wr0, aR2[bb * 2 + 0]);
                    aR2[bb * 2 + 1] = ffma2(hb[bb], wr1, aR2[bb * 2 + 1]);
                    aZ2[bb * 2 + 0] = ffma2(hb[bb], wu0, aZ2[bb * 2 + 0]);
                    aZ2[bb * 2 + 1] = ffma2(hb[bb], wu1, aZ2[bb * 2 + 1]);
                    aN2[bb * 2 + 0] = ffma2(hb[bb], wn0, aN2[bb * 2 + 0]);
                    aN2[bb * 2 + 1] = ffma2(hb[bb], wn1, aN2[bb * 2 + 1]);
                }
            }
        };

        cp_wait<1>(); __syncwarp();     // own chunk 0 landed (warp-local)
        gemm_chunk(0);
        cp_wait<0>(); __syncwarp();     // own chunk 1 landed
        gemm_chunk(32);
    }

    // --- epilogue: x-GEMM (F=4, fp32) + b_ni, then gates + write h_next ---
    float2 xiN2[8];
    float* xiN = (float*)xiN2;
    {
        float4 bn = *(const float4*)&g_bias[3][l * 64 + k0];
#pragma unroll
        for (int bb = 0; bb < 4; bb++) {
            xiN2[bb * 2 + 0] = make_float2(bn.x, bn.y);
            xiN2[bb * 2 + 1] = make_float2(bn.z, bn.w);
        }
        const float* xb = g_xT + (t * NL + l) * (NF * NB);
#pragma unroll
        for (int f = 0; f < 4; f++) {
            float4 xv = *(const float4*)&xb[f * 32 + b0];
            float2 xs[4] = { {xv.x, xv.x}, {xv.y, xv.y}, {xv.z, xv.z}, {xv.w, xv.w} };
            float4 wr = *(const float4*)&w_ri[l * 256 + f * 64 + k0];
            float4 wu = *(const float4*)&w_ui[l * 256 + f * 64 + k0];
            float4 wn = *(const float4*)&w_ni[l * 256 + f * 64 + k0];
            float2 wr0 = make_float2(wr.x, wr.y), wr1 = make_float2(wr.z, wr.w);
            float2 wu0 = make_float2(wu.x, wu.y), wu1 = make_float2(wu.z, wu.w);
            float2 wn0 = make_float2(wn.x, wn.y), wn1 = make_float2(wn.z, wn.w);
#pragma unroll
            for (int bb = 0; bb < 4; bb++) {
                aR2[bb * 2 + 0] = ffma2(xs[bb], wr0, aR2[bb * 2 + 0]);
                aR2[bb * 2 + 1] = ffma2(xs[bb], wr1, aR2[bb * 2 + 1]);
                aZ2[bb * 2 + 0] = ffma2(xs[bb], wu0, aZ2[bb * 2 + 0]);
                aZ2[bb * 2 + 1] = ffma2(xs[bb], wu1, aZ2[bb * 2 + 1]);
                xiN2[bb * 2 + 0] = ffma2(xs[bb], wn0, xiN2[bb * 2 + 0]);
                xiN2[bb * 2 + 1] = ffma2(xs[bb], wn1, xiN2[bb * 2 + 1]);
            }
        }
    }

    const float* hcur = g_h[cur] + l * (NH * NB);
    float* hnxt = g_h[nxt] + l * (NH * NB);
#pragma unroll
    for (int kk = 0; kk < 4; kk++) {
        int k = k0 + kk;
        float holdv[4] = {0.f, 0.f, 0.f, 0.f};
        if (!FIRST) {
            float4 h4 = *(const float4*)&hcur[k * 32 + b0];
            holdv[0] = h4.x; holdv[1] = h4.y; holdv[2] = h4.z; holdv[3] = h4.w;
        }
        float o[4];
#pragma unroll
        for (int bb = 0; bb < 4; bb++) {
            int p = bb * 4 + kk;
            float r = fsigmoid(accR[p]);
            float z = fsigmoid(accZ[p]);
            float n = ftanh_fast(xiN[p] + r * accNH[p]);
            o[bb] = n + z * (holdv[bb] - n);
        }
        *(float4*)&hnxt[k * 32 + b0] = make_float4(o[0], o[1], o[2], o[3]);
    }
}

// ---------------- output head ----------------
__global__ void fc_kernel(const float* __restrict__ w_fc, const float* __restrict__ b_fc,
                          float* __restrict__ out) {
    int l = blockIdx.x;
    int b = threadIdx.x;   // 32 threads
    const float* h = g_h[0] + l * (NH * NB);
    float acc = b_fc[l];
#pragma unroll 8
    for (int k = 0; k < NH; k++) acc += h[k * 32 + b] * w_fc[l * NH + k];
    out[b * NL + l] = acc;   // [B][O=1][L]
}

// ---------------- launch ----------------
#define STEP_SMEM (14336 * 4)   // 56 KB: 48KB weights (4 x 12KB warp slices) + 8KB hatt

static void configure_attrs_once() {
    // Runs on the first kernel_launch call (the harness's correctness run,
    // which precedes graph capture). cudaFuncSetAttribute is not capturable,
    // so it must not execute on the capture call.
    static bool done = false;
    if (done) return;
    cudaFuncSetAttribute(step_kernel<true>,  cudaFuncAttributeMaxDynamicSharedMemorySize, STEP_SMEM);
    cudaFuncSetAttribute(step_kernel<false>, cudaFuncAttributeMaxDynamicSharedMemorySize, STEP_SMEM);
    done = true;
}

extern "C" void kernel_launch(void* const* d_in, const int* in_sizes, int n_in,
                              void* d_out, int out_size) {
    const float* x    = (const float*)d_in[0];
    const float* att  = (const float*)d_in[1];
    const float* w_rh = (const float*)d_in[2];
    const float* b_rh = (const float*)d_in[3];
    const float* w_ri = (const float*)d_in[4];
    const float* b_ri = (const float*)d_in[5];
    const float* w_uh = (const float*)d_in[6];
    const float* b_uh = (const float*)d_in[7];
    const float* w_ui = (const float*)d_in[8];
    const float* b_ui = (const float*)d_in[9];
    const float* w_nh = (const float*)d_in[10];
    const float* b_nh = (const float*)d_in[11];
    const float* w_ni = (const float*)d_in[12];
    const float* b_ni = (const float*)d_in[13];
    const float* w_fc = (const float*)d_in[14];
    const float* b_fc = (const float*)d_in[15];

    configure_attrs_once();

    prep_bias<<<1024, 256>>>(b_rh, b_ri, b_uh, b_ui, b_nh, b_ni);
    prep_x<<<6144, 256>>>(x);

    // t=0: h=0, skip attention + hidden GEMM
    step_kernel<true><<<1024, 128, STEP_SMEM>>>(att, w_rh, w_uh, w_nh, w_ri, w_ui, w_ni, 0, 0, 1);
    for (int t = 1; t < NT; t++) {
        step_kernel<false><<<1024, 128, STEP_SMEM>>>(att, w_rh, w_uh, w_nh, w_ri, w_ui, w_ni,
                                                     t, t & 1, (t + 1) & 1);
    }
    // after t=11 (writes buffer 0)
    fc_kernel<<<1024, 32>>>(w_fc, b_fc, (float*)d_out);
}

// round 9
// speedup vs baseline: 1.9978x; 1.4695x over previous
#include <cuda_runtime.h>
#include <cuda_fp16.h>
#include <cstdint>

#define NL 1024
#define NB 32
#define NT 12
#define NF 4
#define NH 64

// Scratch (static device globals: allocation-free rule)
__device__ float g_h[2][NL * NH * NB];      // hidden, layout [L][H][B], double buffered
__device__ float g_xT[NT * NL * NF * NB];   // x transposed to [T][L][F][B]
__device__ float g_bias[4][NL * NH];        // [0]=b_rh+b_ri, [1]=b_uh+b_ui, [2]=b_nh, [3]=b_ni ; [L][H]
__device__ __half g_wf[NL * 4 * 4 * 3 * 256]; // fragment-packed fp16 hidden weights (25MB)
// g_wf block = (((l*4 + kiter)*4 + warp)*3 + gate), 256 fp16 per block = 32 lanes x 4 b32 regs
// (exact mma.m16n8k16 A-fragment order, so a warp LDG.128 at +lane*16B yields its 4 a-regs)

// packed f32x2 FMA (two independent fp32 lanes)
__device__ __forceinline__ float2 ffma2(float2 a, float2 b, float2 c) {
    unsigned long long ua = *reinterpret_cast<unsigned long long*>(&a);
    unsigned long long ub = *reinterpret_cast<unsigned long long*>(&b);
    unsigned long long uc = *reinterpret_cast<unsigned long long*>(&c);
    unsigned long long ud;
    asm("fma.rn.f32x2 %0, %1, %2, %3;" : "=l"(ud) : "l"(ua), "l"(ub), "l"(uc));
    return *reinterpret_cast<float2*>(&ud);
}

// D(16x8,f32) += A(16x16,f16) @ B(16x8,f16) ; d01 = row g cols (2t,2t+1), d23 = row g+8
__device__ __forceinline__ void mma16816(float2& d01, float2& d23,
                                         uint4 a, uint32_t b0, uint32_t b1) {
    asm volatile(
        "mma.sync.aligned.m16n8k16.row.col.f32.f16.f16.f32 "
        "{%0,%1,%2,%3}, {%4,%5,%6,%7}, {%8,%9}, {%0,%1,%2,%3};"
        : "+f"(d01.x), "+f"(d01.y), "+f"(d23.x), "+f"(d23.y)
        : "r"(a.x), "r"(a.y), "r"(a.z), "r"(a.w), "r"(b0), "r"(b1));
}

__device__ __forceinline__ float fsigmoid(float x) {
    return __fdividef(1.0f, 1.0f + __expf(-x));
}
__device__ __forceinline__ float ftanh_fast(float x) {
    float e = __expf(2.0f * x);
    return 1.0f - __fdividef(2.0f, e + 1.0f);
}

// ---------------- prep kernels ----------------

__global__ void prep_bias(const float* __restrict__ b_rh, const float* __restrict__ b_ri,
                          const float* __restrict__ b_uh, const float* __restrict__ b_ui,
                          const float* __restrict__ b_nh, const float* __restrict__ b_ni) {
    int idx = blockIdx.x * blockDim.x + threadIdx.x;
    if (idx >= 4 * NL * NH) return;
    int q = idx >> 16;
    int r = idx & 65535;
    int l = r >> 6;
    int k = r & 63;
    int src = k * NL + l;
    float v;
    if (q == 0)      v = b_rh[src] + b_ri[src];
    else if (q == 1) v = b_uh[src] + b_ui[src];
    else if (q == 2) v = b_nh[src];
    else             v = b_ni[src];
    g_bias[q][r] = v;
}

__global__ void prep_x(const float* __restrict__ x) {
    int idx = blockIdx.x * blockDim.x + threadIdx.x;
    if (idx >= NT * NL * NF * NB) return;
    int b = idx & 31;
    int f = (idx >> 5) & 3;
    int l = (idx >> 7) & 1023;
    int t = idx >> 17;
    g_xT[idx] = x[((b * NT + t) * NF + f) * NL + l];
}

// pack hidden-gate weights into mma A-fragment order, fp16.
// One thread per u32 (= __half2 = one a-reg). a-reg s of lane:
//   s=0: A[gr][2t,2t+1]  s=1: A[gr+8][..]  s=2: A[gr][2t+8,2t+9]  s=3: A[gr+8][+8]
// A row = gru-output k (= warp*16 + row), A col = h (= kiter*16 + col). W is [l][h][k].
__global__ void prep_wfrag(const float* __restrict__ w_rh, const float* __restrict__ w_uh,
                           const float* __restrict__ w_nh) {
    int p = blockIdx.x * blockDim.x + threadIdx.x;   // total NL*4*4*3*128 u32
    if (p >= NL * 4 * 4 * 3 * 128) return;
    int s    = p & 3;
    int lane = (p >> 2) & 31;
    int blk  = p >> 7;
    int gate = blk % 3;
    int rest = blk / 3;
    int warp  = rest & 3;
    int kiter = (rest >> 2) & 3;
    int l     = rest >> 4;
    int gr  = lane >> 2;
    int tig = lane & 3;
    int row = warp * 16 + gr + ((s & 1) ? 8 : 0);       // gru k
    int col = kiter * 16 + tig * 2 + ((s & 2) ? 8 : 0); // h
    const float* W = (gate == 0) ? w_rh : (gate == 1) ? w_uh : w_nh;
    const float* src = W + l * 4096 + col * 64 + row;
    __half2 v = __floats2half2_rn(src[0], src[64]);     // (h, h+1), same k
    reinterpret_cast<__half2*>(g_wf)[p] = v;
}

// ---------------- GRU step kernel ----------------
// block = link l, 128 threads, 4 CTAs/SM. Warp w owns gate-rows [w*16, w*16+16) of
// all 3 gates. GEMM on tensor pipe: mma.m16n8k16, A-frags straight from g_wf via
// coalesced LDG.128 (no weight smem), B-frags from fp16 hatt smem [b][72]
// (144B rows -> conflict-free LDS.32). fp32 accumulators; epilogue thread-local.

template <bool FIRST>
__global__ void __launch_bounds__(128, 4)
step_kernel(const float* __restrict__ att,
            const float* __restrict__ w_ri, const float* __restrict__ w_ui,
            const float* __restrict__ w_ni,
            int t, int cur, int nxt) {
    __shared__ __half sH[NB * 72];   // hatt fp16, [b][72] (rows padded to 144B)

    const int l    = blockIdx.x;
    const int tid  = threadIdx.x;
    const int lane = tid & 31;
    const int warp = tid >> 5;
    const int gr   = lane >> 2;       // mma groupID
    const int tig  = lane & 3;        // thread in group
    const int k0   = warp * 16 + gr;  // gru output rows owned: k0, k0+8
    const int k1   = k0 + 8;
    const int bq   = tig * 2;         // b pair base within an N-tile

    if (!FIRST) {
        // graph attention -> fp16 smem [b][h]
        float a0 = att[l * NL + l];
        float am = (l > 0)      ? att[l * NL + l - 1] : 0.0f;
        float ap = (l < NL - 1) ? att[l * NL + l + 1] : 0.0f;
        const int lm = (l > 0) ? l - 1 : l;
        const int lp = (l < NL - 1) ? l + 1 : l;
        const float4* hm = (const float4*)(g_h[cur] + lm * (NH * NB));
        const float4* hc = (const float4*)(g_h[cur] + l  * (NH * NB));
        const float4* hp = (const float4*)(g_h[cur] + lp * (NH * NB));
#pragma unroll
        for (int i = 0; i < 4; i++) {
            int j = tid + i * 128;
            int h = j >> 3, b0 = (j & 7) * 4;
            float4 m = hm[j], c4 = hc[j], p = hp[j];
            sH[(b0 + 0) * 72 + h] = __float2half(am * m.x + a0 * c4.x + ap * p.x);
            sH[(b0 + 1) * 72 + h] = __float2half(am * m.y + a0 * c4.y + ap * p.y);
            sH[(b0 + 2) * 72 + h] = __float2half(am * m.z + a0 * c4.z + ap * p.z);
            sH[(b0 + 3) * 72 + h] = __float2half(am * m.w + a0 * c4.w + ap * p.w);
        }
    }

    // accumulators [kreg][nt]: float2 over b pair (bq, bq+1); init from combined biases
    float2 dR[2][4], dZ[2][4], dN[2][4];
    {
        float br0 = g_bias[0][l * 64 + k0], br1 = g_bias[0][l * 64 + k1];
        float bz0 = g_bias[1][l * 64 + k0], bz1 = g_bias[1][l * 64 + k1];
        float bh0 = g_bias[2][l * 64 + k0], bh1 = g_bias[2][l * 64 + k1];
#pragma unroll
        for (int nt = 0; nt < 4; nt++) {
            dR[0][nt] = make_float2(br0, br0);  dR[1][nt] = make_float2(br1, br1);
            dZ[0][nt] = make_float2(bz0, bz0);  dZ[1][nt] = make_float2(bz1, bz1);
            dN[0][nt] = make_float2(bh0, bh0);  dN[1][nt] = make_float2(bh1, bh1);
        }
    }

    if (!FIRST) {
        __syncthreads();   // hatt visible
        // A-frag base for this warp: block (((l*4+kit)*4+warp)*3+gate) = (l*16+warp)*3 + kit*12 + gate
        const uint4* wbase = (const uint4*)g_wf + (uint32_t)((l * 16 + warp) * 3) * 32 + lane;
#pragma unroll
        for (int kit = 0; kit < 4; kit++) {
            uint4 Ar = wbase[(kit * 12 + 0) * 32];
            uint4 Au = wbase[(kit * 12 + 1) * 32];
            uint4 An = wbase[(kit * 12 + 2) * 32];
            const int hb = kit * 16 + bq;   // B rows (h) for this thread: hb, hb+1, hb+8, hb+9
#pragma unroll
            for (int nt = 0; nt < 4; nt++) {
                int bb = nt * 8 + gr;       // B col (b) for this thread
                uint32_t b0 = *(const uint32_t*)&sH[bb * 72 + hb];
                uint32_t b1 = *(const uint32_t*)&sH[bb * 72 + hb + 8];
                mma16816(dR[0][nt], dR[1][nt], Ar, b0, b1);
                mma16816(dZ[0][nt], dZ[1][nt], Au, b0, b1);
                mma16816(dN[0][nt], dN[1][nt], An, b0, b1);
            }
        }
    }

    // --- epilogue: x-GEMM (F=4, fp32) + b_ni, then gates + write h_next ---
    float2 xiN[2][4];
    {
        float bn0 = g_bias[3][l * 64 + k0], bn1 = g_bias[3][l * 64 + k1];
#pragma unroll
        for (int nt = 0; nt < 4; nt++) {
            xiN[0][nt] = make_float2(bn0, bn0);
            xiN[1][nt] = make_float2(bn1, bn1);
        }
    }
    const float* xb = g_xT + (t * NL + l) * (NF * NB);
#pragma unroll
    for (int f = 0; f < 4; f++) {
        float wr0 = w_ri[l * 256 + f * 64 + k0], wr1 = w_ri[l * 256 + f * 64 + k1];
        float wu0 = w_ui[l * 256 + f * 64 + k0], wu1 = w_ui[l * 256 + f * 64 + k1];
        float wn0 = w_ni[l * 256 + f * 64 + k0], wn1 = w_ni[l * 256 + f * 64 + k1];
        float2 wr2a = make_float2(wr0, wr0), wr2b = make_float2(wr1, wr1);
        float2 wu2a = make_float2(wu0, wu0), wu2b = make_float2(wu1, wu1);
        float2 wn2a = make_float2(wn0, wn0), wn2b = make_float2(wn1, wn1);
#pragma unroll
        for (int nt = 0; nt < 4; nt++) {
            float2 xv = *(const float2*)&xb[f * 32 + nt * 8 + bq];
            dR[0][nt]  = ffma2(xv, wr2a, dR[0][nt]);
            dR[1][nt]  = ffma2(xv, wr2b, dR[1][nt]);
            dZ[0][nt]  = ffma2(xv, wu2a, dZ[0][nt]);
            dZ[1][nt]  = ffma2(xv, wu2b, dZ[1][nt]);
            xiN[0][nt] = ffma2(xv, wn2a, xiN[0][nt]);
            xiN[1][nt] = ffma2(xv, wn2b, xiN[1][nt]);
        }
    }

    const float* hcur = g_h[cur] + l * (NH * NB);
    float* hnxt = g_h[nxt] + l * (NH * NB);
#pragma unroll
    for (int kreg = 0; kreg < 2; kreg++) {
        int k = kreg ? k1 : k0;
#pragma unroll
        for (int nt = 0; nt < 4; nt++) {
            int b = nt * 8 + bq;
            float2 hold = make_float2(0.0f, 0.0f);
            if (!FIRST) hold = *(const float2*)&hcur[k * 32 + b];
            float r0 = fsigmoid(dR[kreg][nt].x), r1 = fsigmoid(dR[kreg][nt].y);
            float z0 = fsigmoid(dZ[kreg][nt].x), z1 = fsigmoid(dZ[kreg][nt].y);
            float n0 = ftanh_fast(xiN[kreg][nt].x + r0 * dN[kreg][nt].x);
            float n1 = ftanh_fast(xiN[kreg][nt].y + r1 * dN[kreg][nt].y);
            float2 o = make_float2(n0 + z0 * (hold.x - n0), n1 + z1 * (hold.y - n1));
            *(float2*)&hnxt[k * 32 + b] = o;
        }
    }
}

// ---------------- output head ----------------
__global__ void fc_kernel(const float* __restrict__ w_fc, const float* __restrict__ b_fc,
                          float* __restrict__ out) {
    int l = blockIdx.x;
    int b = threadIdx.x;   // 32 threads
    const float* h = g_h[0] + l * (NH * NB);
    float acc = b_fc[l];
#pragma unroll 8
    for (int k = 0; k < NH; k++) acc += h[k * 32 + b] * w_fc[l * NH + k];
    out[b * NL + l] = acc;   // [B][O=1][L]
}

// ---------------- launch ----------------
extern "C" void kernel_launch(void* const* d_in, const int* in_sizes, int n_in,
                              void* d_out, int out_size) {
    const float* x    = (const float*)d_in[0];
    const float* att  = (const float*)d_in[1];
    const float* w_rh = (const float*)d_in[2];
    const float* b_rh = (const float*)d_in[3];
    const float* w_ri = (const float*)d_in[4];
    const float* b_ri = (const float*)d_in[5];
    const float* w_uh = (const float*)d_in[6];
    const float* b_uh = (const float*)d_in[7];
    const float* w_ui = (const float*)d_in[8];
    const float* b_ui = (const float*)d_in[9];
    const float* w_nh = (const float*)d_in[10];
    const float* b_nh = (const float*)d_in[11];
    const float* w_ni = (const float*)d_in[12];
    const float* b_ni = (const float*)d_in[13];
    const float* w_fc = (const float*)d_in[14];
    const float* b_fc = (const float*)d_in[15];

    prep_bias<<<1024, 256>>>(b_rh, b_ri, b_uh, b_ui, b_nh, b_ni);
    prep_x<<<6144, 256>>>(x);
    prep_wfrag<<<24576, 256>>>(w_rh, w_uh, w_nh);

    // t=0: h=0, skip attention + hidden GEMM
    step_kernel<true><<<1024, 128>>>(att, w_ri, w_ui, w_ni, 0, 0, 1);
    for (int t = 1; t < NT; t++) {
        step_kernel<false><<<1024, 128>>>(att, w_ri, w_ui, w_ni, t, t & 1, (t + 1) & 1);
    }
    // after t=11 (writes buffer 0)
    fc_kernel<<<1024, 32>>>(w_fc, b_fc, (float*)d_out);
}

// round 10
// speedup vs baseline: 2.0968x; 1.0495x over previous
#include <cuda_runtime.h>
#include <cuda_fp16.h>
#include <cstdint>

#define NL 1024
#define NB 32
#define NT 12
#define NF 4
#define NH 64
#define NC 512   // CTAs in fused kernel, 2 links each

// Scratch (static device globals: allocation-free rule)
__device__ float g_h[2][NL * NH * NB];      // hidden, layout [L][H][B], double buffered
__device__ float g_xT[NT * NL * NF * NB];   // x transposed to [T][L][F][B]
__device__ float g_bias[4][NL * NH];        // [0]=b_rh+b_ri, [1]=b_uh+b_ui, [2]=b_nh, [3]=b_ni ; [L][H]
__device__ __half g_wf[NL * 4 * 4 * 3 * 256]; // fragment-packed fp16 hidden weights (25MB)
__device__ int g_flag[NC * 32];             // per-CTA progress flags, 128B stride

// packed f32x2 FMA (two independent fp32 lanes)
__device__ __forceinline__ float2 ffma2(float2 a, float2 b, float2 c) {
    unsigned long long ua = *reinterpret_cast<unsigned long long*>(&a);
    unsigned long long ub = *reinterpret_cast<unsigned long long*>(&b);
    unsigned long long uc = *reinterpret_cast<unsigned long long*>(&c);
    unsigned long long ud;
    asm("fma.rn.f32x2 %0, %1, %2, %3;" : "=l"(ud) : "l"(ua), "l"(ub), "l"(uc));
    return *reinterpret_cast<float2*>(&ud);
}

// D(16x8,f32) += A(16x16,f16) @ B(16x8,f16)
__device__ __forceinline__ void mma16816(float2& d01, float2& d23,
                                         uint4 a, uint32_t b0, uint32_t b1) {
    asm volatile(
        "mma.sync.aligned.m16n8k16.row.col.f32.f16.f16.f32 "
        "{%0,%1,%2,%3}, {%4,%5,%6,%7}, {%8,%9}, {%0,%1,%2,%3};"
        : "+f"(d01.x), "+f"(d01.y), "+f"(d23.x), "+f"(d23.y)
        : "r"(a.x), "r"(a.y), "r"(a.z), "r"(a.w), "r"(b0), "r"(b1));
}

__device__ __forceinline__ float fsigmoid(float x) {
    return __fdividef(1.0f, 1.0f + __expf(-x));
}
__device__ __forceinline__ float ftanh_fast(float x) {
    float e = __expf(2.0f * x);
    return 1.0f - __fdividef(2.0f, e + 1.0f);
}

// ---------------- prep kernels ----------------

__global__ void prep_bias(const float* __restrict__ b_rh, const float* __restrict__ b_ri,
                          const float* __restrict__ b_uh, const float* __restrict__ b_ui,
                          const float* __restrict__ b_nh, const float* __restrict__ b_ni) {
    int idx = blockIdx.x * blockDim.x + threadIdx.x;
    if (idx < NC * 32) g_flag[idx] = 0;      // reset sync flags every launch
    if (idx >= 4 * NL * NH) return;
    int q = idx >> 16;
    int r = idx & 65535;
    int l = r >> 6;
    int k = r & 63;
    int src = k * NL + l;
    float v;
    if (q == 0)      v = b_rh[src] + b_ri[src];
    else if (q == 1) v = b_uh[src] + b_ui[src];
    else if (q == 2) v = b_nh[src];
    else             v = b_ni[src];
    g_bias[q][r] = v;
}

__global__ void prep_x(const float* __restrict__ x) {
    int idx = blockIdx.x * blockDim.x + threadIdx.x;
    if (idx >= NT * NL * NF * NB) return;
    int b = idx & 31;
    int f = (idx >> 5) & 3;
    int l = (idx >> 7) & 1023;
    int t = idx >> 17;
    g_xT[idx] = x[((b * NT + t) * NF + f) * NL + l];
}

// pack hidden-gate weights into mma A-fragment order, fp16 (validated in R9)
__global__ void prep_wfrag(const float* __restrict__ w_rh, const float* __restrict__ w_uh,
                           const float* __restrict__ w_nh) {
    int p = blockIdx.x * blockDim.x + threadIdx.x;
    if (p >= NL * 4 * 4 * 3 * 128) return;
    int s    = p & 3;
    int lane = (p >> 2) & 31;
    int blk  = p >> 7;
    int gate = blk % 3;
    int rest = blk / 3;
    int warp  = rest & 3;
    int kiter = (rest >> 2) & 3;
    int l     = rest >> 4;
    int gr  = lane >> 2;
    int tig = lane & 3;
    int row = warp * 16 + gr + ((s & 1) ? 8 : 0);
    int col = kiter * 16 + tig * 2 + ((s & 2) ? 8 : 0);
    const float* W = (gate == 0) ? w_rh : (gate == 1) ? w_uh : w_nh;
    const float* src = W + l * 4096 + col * 64 + row;
    __half2 v = __floats2half2_rn(src[0], src[64]);
    reinterpret_cast<__half2*>(g_wf)[p] = v;
}

// ---------------- fused persistent GRU kernel ----------------
// CTA c owns links {2c, 2c+1}. All 12 timesteps in one launch; cross-CTA
// dependence is only +-1 link, enforced via per-CTA progress flags
// (store-release after own h writes, spin on flag[c-1], flag[c+1]).
// Grid co-residency: 512 CTAs, launch_bounds(128,4) => 4 CTAs/SM * 148 SMs = 592.
// ALL g_h accesses use __ldcg (L1 is stale across steps); weights/x/bias are
// immutable during the kernel so default (L1) caching is safe and beneficial.

__global__ void __launch_bounds__(128, 4)
fused_kernel(const float* __restrict__ att,
             const float* __restrict__ w_ri, const float* __restrict__ w_ui,
             const float* __restrict__ w_ni,
             const float* __restrict__ w_fc, const float* __restrict__ b_fc,
             float* __restrict__ out) {
    __shared__ __half sH[NB * 72];   // hatt fp16, [b][72] (144B rows)

    const int c    = blockIdx.x;
    const int tid  = threadIdx.x;
    const int lane = tid & 31;
    const int warp = tid >> 5;
    const int gr   = lane >> 2;
    const int tig  = lane & 3;
    const int k0   = warp * 16 + gr;
    const int k1   = k0 + 8;
    const int bq   = tig * 2;
    const int l0   = 2 * c;

    // ---- per-link loop invariants hoisted into registers ----
    float a0[2], am[2], ap[2];
    float bR0[2], bR1[2], bZ0[2], bZ1[2], bH0[2], bH1[2], bN0[2], bN1[2];
#pragma unroll
    for (int li = 0; li < 2; li++) {
        int l = l0 + li;
        a0[li] = att[l * NL + l];
        am[li] = (l > 0)      ? att[l * NL + l - 1] : 0.0f;
        ap[li] = (l < NL - 1) ? att[l * NL + l + 1] : 0.0f;
        bR0[li] = g_bias[0][l * 64 + k0];  bR1[li] = g_bias[0][l * 64 + k1];
        bZ0[li] = g_bias[1][l * 64 + k0];  bZ1[li] = g_bias[1][l * 64 + k1];
        bH0[li] = g_bias[2][l * 64 + k0];  bH1[li] = g_bias[2][l * 64 + k1];
        bN0[li] = g_bias[3][l * 64 + k0];  bN1[li] = g_bias[3][l * 64 + k1];
    }

    for (int t = 0; t < NT; t++) {
        const int cur = t & 1, nxt = cur ^ 1;
#pragma unroll 1
        for (int li = 0; li < 2; li++) {
            const int l = l0 + li;

            if (t > 0) {
                __syncthreads();   // previous sH consumers done
                const int lm = (l > 0) ? l - 1 : l;
                const int lp = (l < NL - 1) ? l + 1 : l;
                const float4* hm = (const float4*)(g_h[cur] + lm * (NH * NB));
                const float4* hc = (const float4*)(g_h[cur] + l  * (NH * NB));
                const float4* hp = (const float4*)(g_h[cur] + lp * (NH * NB));
#pragma unroll
                for (int i = 0; i < 4; i++) {
                    int j = tid + i * 128;
                    int h = j >> 3, b0 = (j & 7) * 4;
                    float4 m = __ldcg(hm + j), c4 = __ldcg(hc + j), p = __ldcg(hp + j);
                    sH[(b0 + 0) * 72 + h] = __float2half(am[li] * m.x + a0[li] * c4.x + ap[li] * p.x);
                    sH[(b0 + 1) * 72 + h] = __float2half(am[li] * m.y + a0[li] * c4.y + ap[li] * p.y);
                    sH[(b0 + 2) * 72 + h] = __float2half(am[li] * m.z + a0[li] * c4.z + ap[li] * p.z);
                    sH[(b0 + 3) * 72 + h] = __float2half(am[li] * m.w + a0[li] * c4.w + ap[li] * p.w);
                }
                __syncthreads();   // sH ready
            }

            // accumulators init from hoisted biases
            float2 dR[2][4], dZ[2][4], dN[2][4], xiN[2][4];
#pragma unroll
            for (int nt = 0; nt < 4; nt++) {
                dR[0][nt] = make_float2(bR0[li], bR0[li]);  dR[1][nt] = make_float2(bR1[li], bR1[li]);
                dZ[0][nt] = make_float2(bZ0[li], bZ0[li]);  dZ[1][nt] = make_float2(bZ1[li], bZ1[li]);
                dN[0][nt] = make_float2(bH0[li], bH0[li]);  dN[1][nt] = make_float2(bH1[li], bH1[li]);
                xiN[0][nt] = make_float2(bN0[li], bN0[li]); xiN[1][nt] = make_float2(bN1[li], bN1[li]);
            }

            if (t > 0) {
                const uint4* wbase = (const uint4*)g_wf + (uint32_t)((l * 16 + warp) * 3) * 32 + lane;
#pragma unroll
                for (int kit = 0; kit < 4; kit++) {
                    uint4 Ar = wbase[(kit * 12 + 0) * 32];
                    uint4 Au = wbase[(kit * 12 + 1) * 32];
                    uint4 An = wbase[(kit * 12 + 2) * 32];
                    const int hb = kit * 16 + bq;
#pragma unroll
                    for (int nt = 0; nt < 4; nt++) {
                        int bb = nt * 8 + gr;
                        uint32_t b0 = *(const uint32_t*)&sH[bb * 72 + hb];
                        uint32_t b1 = *(const uint32_t*)&sH[bb * 72 + hb + 8];
                        mma16816(dR[0][nt], dR[1][nt], Ar, b0, b1);
                        mma16816(dZ[0][nt], dZ[1][nt], Au, b0, b1);
                        mma16816(dN[0][nt], dN[1][nt], An, b0, b1);
                    }
                }
            }

            // x-GEMM (F=4, fp32; weights/x immutable -> L1-cached)
            const float* xb = g_xT + (t * NL + l) * (NF * NB);
#pragma unroll
            for (int f = 0; f < 4; f++) {
                float wr0 = w_ri[l * 256 + f * 64 + k0], wr1 = w_ri[l * 256 + f * 64 + k1];
                float wu0 = w_ui[l * 256 + f * 64 + k0], wu1 = w_ui[l * 256 + f * 64 + k1];
                float wn0 = w_ni[l * 256 + f * 64 + k0], wn1 = w_ni[l * 256 + f * 64 + k1];
                float2 wr2a = make_float2(wr0, wr0), wr2b = make_float2(wr1, wr1);
                float2 wu2a = make_float2(wu0, wu0), wu2b = make_float2(wu1, wu1);
                float2 wn2a = make_float2(wn0, wn0), wn2b = make_float2(wn1, wn1);
#pragma unroll
                for (int nt = 0; nt < 4; nt++) {
                    float2 xv = *(const float2*)&xb[f * 32 + nt * 8 + bq];
                    dR[0][nt]  = ffma2(xv, wr2a, dR[0][nt]);
                    dR[1][nt]  = ffma2(xv, wr2b, dR[1][nt]);
                    dZ[0][nt]  = ffma2(xv, wu2a, dZ[0][nt]);
                    dZ[1][nt]  = ffma2(xv, wu2b, dZ[1][nt]);
                    xiN[0][nt] = ffma2(xv, wn2a, xiN[0][nt]);
                    xiN[1][nt] = ffma2(xv, wn2b, xiN[1][nt]);
                }
            }

            // gates + h_next
            const float* hcur = g_h[cur] + l * (NH * NB);
            float* hnxt = g_h[nxt] + l * (NH * NB);
#pragma unroll
            for (int kreg = 0; kreg < 2; kreg++) {
                int k = kreg ? k1 : k0;
#pragma unroll
                for (int nt = 0; nt < 4; nt++) {
                    int b = nt * 8 + bq;
                    float2 hold = make_float2(0.0f, 0.0f);
                    if (t > 0) hold = __ldcg((const float2*)&hcur[k * 32 + b]);
                    float r0 = fsigmoid(dR[kreg][nt].x), r1 = fsigmoid(dR[kreg][nt].y);
                    float z0 = fsigmoid(dZ[kreg][nt].x), z1 = fsigmoid(dZ[kreg][nt].y);
                    float n0 = ftanh_fast(xiN[kreg][nt].x + r0 * dN[kreg][nt].x);
                    float n1 = ftanh_fast(xiN[kreg][nt].y + r1 * dN[kreg][nt].y);
                    float2 o = make_float2(n0 + z0 * (hold.x - n0), n1 + z1 * (hold.y - n1));
                    *(float2*)&hnxt[k * 32 + b] = o;
                }
            }
        }

        // ---- neighbor sync (wavefront): publish step t, wait for c-1 / c+1 ----
        if (t < NT - 1) {
            __threadfence();        // every thread: my h stores reach L2 before flag
            __syncthreads();
            if (tid == 0) {
                *(volatile int*)&g_flag[c * 32] = t + 1;
                if (c > 0)
                    while (*(volatile int*)&g_flag[(c - 1) * 32] <= t) __nanosleep(64);
                if (c < NC - 1)
                    while (*(volatile int*)&g_flag[(c + 1) * 32] <= t) __nanosleep(64);
            }
            __syncthreads();
        }
    }

    // ---- fc head (own links only; h final lives in g_h[0] after t=11) ----
    __syncthreads();
    if (tid < 64) {
        int li = tid >> 5, b = tid & 31;
        int l = l0 + li;
        const float* h = g_h[0] + l * (NH * NB);
        float acc = b_fc[l];
#pragma unroll 8
        for (int k = 0; k < NH; k++) acc += __ldcg(&h[k * 32 + b]) * w_fc[l * NH + k];
        out[b * NL + l] = acc;
    }
}

// ---------------- launch ----------------
extern "C" void kernel_launch(void* const* d_in, const int* in_sizes, int n_in,
                              void* d_out, int out_size) {
    const float* x    = (const float*)d_in[0];
    const float* att  = (const float*)d_in[1];
    const float* w_rh = (const float*)d_in[2];
    const float* b_rh = (const float*)d_in[3];
    const float* w_ri = (const float*)d_in[4];
    const float* b_ri = (const float*)d_in[5];
    const float* w_uh = (const float*)d_in[6];
    const float* b_uh = (const float*)d_in[7];
    const float* w_ui = (const float*)d_in[8];
    const float* b_ui = (const float*)d_in[9];
    const float* w_nh = (const float*)d_in[10];
    const float* b_nh = (const float*)d_in[11];
    const float* w_ni = (const float*)d_in[12];
    const float* b_ni = (const float*)d_in[13];
    const float* w_fc = (const float*)d_in[14];
    const float* b_fc = (const float*)d_in[15];

    prep_bias<<<1024, 256>>>(b_rh, b_ri, b_uh, b_ui, b_nh, b_ni);
    prep_x<<<6144, 256>>>(x);
    prep_wfrag<<<24576, 256>>>(w_rh, w_uh, w_nh);

    fused_kernel<<<NC, 128>>>(att, w_ri, w_ui, w_ni, w_fc, b_fc, (float*)d_out);
}

// round 11
// speedup vs baseline: 2.3897x; 1.1397x over previous
#include <cuda_runtime.h>
#include <cuda_fp16.h>
#include <cstdint>

#define NL 1024
#define NB 32
#define NT 12
#define NF 4
#define NH 64
#define NC 512          // CTAs, 2 links each
#define SHS 88          // sH row stride in halfs (per batch row)
#define SHL (32 * SHS)  // per-link sH halfs

// Scratch (static device globals: allocation-free rule)
__device__ float g_h[2][NL * NH * NB];      // hidden [L][H][B], double buffered (neighbor exchange)
__device__ float g_xT[NT * NL * NF * NB];   // x transposed to [T][L][F][B]
__device__ __half g_wf[NL * 4 * 15 * 256];  // A-fragments: ((l*4+warp)*15 + kit*3 + gate) blocks of 256 half
__device__ int g_flag[NC * 32];             // per-CTA progress flags, 128B stride

// packed f32x2 FMA
__device__ __forceinline__ float2 ffma2(float2 a, float2 b, float2 c) {
    unsigned long long ua = *reinterpret_cast<unsigned long long*>(&a);
    unsigned long long ub = *reinterpret_cast<unsigned long long*>(&b);
    unsigned long long uc = *reinterpret_cast<unsigned long long*>(&c);
    unsigned long long ud;
    asm("fma.rn.f32x2 %0, %1, %2, %3;" : "=l"(ud) : "l"(ua), "l"(ub), "l"(uc));
    return *reinterpret_cast<float2*>(&ud);
}

// D(16x8,f32) += A(16x16,f16) @ B(16x8,f16)
__device__ __forceinline__ void mma16816(float2& d01, float2& d23,
                                         uint4 a, uint32_t b0, uint32_t b1) {
    asm volatile(
        "mma.sync.aligned.m16n8k16.row.col.f32.f16.f16.f32 "
        "{%0,%1,%2,%3}, {%4,%5,%6,%7}, {%8,%9}, {%0,%1,%2,%3};"
        : "+f"(d01.x), "+f"(d01.y), "+f"(d23.x), "+f"(d23.y)
        : "r"(a.x), "r"(a.y), "r"(a.z), "r"(a.w), "r"(b0), "r"(b1));
}

__device__ __forceinline__ float fsigmoid(float x) {
    return __fdividef(1.0f, 1.0f + __expf(-x));
}
__device__ __forceinline__ float ftanh_fast(float x) {
    float e = __expf(2.0f * x);
    return 1.0f - __fdividef(2.0f, e + 1.0f);
}

// ---------------- prep kernels ----------------

__global__ void prep_x(const float* __restrict__ x) {
    int idx = blockIdx.x * blockDim.x + threadIdx.x;
    if (idx < NC * 32) g_flag[idx] = 0;          // reset wavefront flags each replay
    if (idx >= NT * NL * NF * NB) return;
    int b = idx & 31;
    int f = (idx >> 5) & 3;
    int l = (idx >> 7) & 1023;
    int t = idx >> 17;
    g_xT[idx] = x[((b * NT + t) * NF + f) * NL + l];
}

// hidden-gate weights -> A-fragments (kits 0..3), smem-staged for coalescing.
// Fragment content mapping identical to the R9-validated packer.
__global__ void prep_wfrag_h(const float* __restrict__ w_rh, const float* __restrict__ w_uh,
                             const float* __restrict__ w_nh) {
    __shared__ float sm[4096];
    int bid = blockIdx.x;                // l*3 + gate
    int gate = bid % 3, l = bid / 3;
    int tid = threadIdx.x;               // 256
    const float* W = (gate == 0) ? w_rh : (gate == 1) ? w_uh : w_nh;
    const float4* src = (const float4*)(W + l * 4096);
    float4* dsm = (float4*)sm;
#pragma unroll
    for (int i = 0; i < 4; i++) dsm[tid + i * 256] = src[tid + i * 256];
    __syncthreads();
#pragma unroll
    for (int i = 0; i < 2; i++) {
        int e = tid + i * 256;           // 0..511
        int fb = e >> 5;                 // 0..15 : kit*4 + wm
        int kit = fb >> 2, wm = fb & 3;
        int lane = e & 31, gr = lane >> 2, tig = lane & 3;
        uint32_t v[4];
#pragma unroll
        for (int s = 0; s < 4; s++) {
            int row = wm * 16 + gr + ((s & 1) ? 8 : 0);   // gru output k
            int col = kit * 16 + tig * 2 + ((s & 2) ? 8 : 0); // h input
            __half2 h = __floats2half2_rn(sm[col * 64 + row], sm[(col + 1) * 64 + row]);
            v[s] = *(uint32_t*)&h;
        }
        ((uint4*)g_wf)[((l * 4 + wm) * 15 + kit * 3 + gate) * 32 + lane] =
            make_uint4(v[0], v[1], v[2], v[3]);
    }
}

// x-weights + biases -> A-fragments (kit 4).
// A cols 64..67 = w_xi[f][k]; col 68 = bias[k]; cols 69..79 = 0.
// gate0: w_ri, b_rh+b_ri ; gate1: w_ui, b_uh+b_ui ; gate2: w_ni, b_ni.
__global__ void prep_wfrag_x(const float* __restrict__ w_ri, const float* __restrict__ w_ui,
                             const float* __restrict__ w_ni,
                             const float* __restrict__ b_rh, const float* __restrict__ b_ri,
                             const float* __restrict__ b_uh, const float* __restrict__ b_ui,
                             const float* __restrict__ b_ni) {
    int bid = blockIdx.x;                // l*3 + gate
    int gate = bid % 3, l = bid / 3;
    int tid = threadIdx.x;               // 128
    int wm = tid >> 5, lane = tid & 31, gr = lane >> 2, tig = lane & 3;
    const float* Wx = (gate == 0) ? w_ri : (gate == 1) ? w_ui : w_ni;
    uint32_t v[4];
#pragma unroll
    for (int s = 0; s < 4; s++) {
        int row = wm * 16 + gr + ((s & 1) ? 8 : 0);
        int cb = 64 + tig * 2 + ((s & 2) ? 8 : 0);
        float f[2];
#pragma unroll
        for (int j = 0; j < 2; j++) {
            int cc = cb + j;
            float val = 0.0f;
            if (cc < 68) {
                val = Wx[l * 256 + (cc - 64) * 64 + row];
            } else if (cc == 68) {
                if (gate == 0)      val = b_rh[row * NL + l] + b_ri[row * NL + l];
                else if (gate == 1) val = b_uh[row * NL + l] + b_ui[row * NL + l];
                else                val = b_ni[row * NL + l];
            }
            f[j] = val;
        }
        __half2 h = __floats2half2_rn(f[0], f[1]);
        v[s] = *(uint32_t*)&h;
    }
    ((uint4*)g_wf)[((l * 4 + wm) * 15 + 12 + gate) * 32 + lane] =
        make_uint4(v[0], v[1], v[2], v[3]);
}

// ---------------- fused persistent GRU kernel ----------------
// CTA c owns links {2c, 2c+1}; h(t) for own links lives in REGISTERS (the epilogue
// owner thread is also the hold consumer and supplies both intra-CTA terms of the
// attention mix). Only the 2 halo links are read from gmem (L2) per step.
// x-GEMM + biases folded into MMA kit4 via sH rows 64..79 (x, 1.0, zeros).
// Wavefront sync via per-CTA flags; 512 CTAs co-resident (4/SM * 148 = 592).

__global__ void __launch_bounds__(128, 4)
fused_kernel(const float* __restrict__ att, const float* __restrict__ b_nh,
             const float* __restrict__ w_fc, const float* __restrict__ b_fc,
             float* __restrict__ out) {
    __shared__ __half sH[2 * SHL];   // per-link B operand: [b][88] halfs

    const int c = blockIdx.x, tid = threadIdx.x;
    const int lane = tid & 31, warp = tid >> 5;
    const int gr = lane >> 2, tig = lane & 3;
    const int k0 = warp * 16 + gr, k1 = k0 + 8;
    const int bq = tig * 2;
    const int l0 = 2 * c;

    // constant sH rows: row 68 = 1.0 (bias), rows 69..79 = 0 (written once)
    for (int e = tid; e < 2 * 32 * 12; e += 128) {
        int li = e / 384, rem = e % 384;
        int b = rem / 12, row = 68 + rem % 12;
        sH[li * SHL + b * SHS + row] = (row == 68) ? __float2half(1.0f) : __half(0);
    }

    // attention coeffs (hoisted)
    float a0c[2], amc[2], apc[2];
#pragma unroll
    for (int li = 0; li < 2; li++) {
        int l = l0 + li;
        a0c[li] = att[l * NL + l];
        amc[li] = (l > 0)      ? att[l * NL + l - 1] : 0.0f;
        apc[li] = (l < NL - 1) ? att[l * NL + l + 1] : 0.0f;
    }
    const int lm = (l0 > 0) ? l0 - 1 : l0;           // left halo (clamped; coeff 0 at edge)
    const int lp = (l0 + 2 < NL) ? l0 + 2 : l0 + 1;  // right halo (clamped; coeff 0 at edge)

    // own hidden state in registers: o[li][kreg][nt] = h[l0+li][k][b..b+1]
    float2 o[2][2][4];
#pragma unroll
    for (int li = 0; li < 2; li++)
#pragma unroll
        for (int kr = 0; kr < 2; kr++)
#pragma unroll
            for (int nt = 0; nt < 4; nt++) o[li][kr][nt] = make_float2(0.0f, 0.0f);

    for (int t = 0; t < NT; t++) {
        const int cur = t & 1, nxt = cur ^ 1;

        // ---- Phase A: write sH (x rows every step; hatt rows for t>0) ----
#pragma unroll
        for (int i = 0; i < 2; i++) {
            int e = tid + i * 128;
            int li = e >> 7, f = (e >> 5) & 3, b = e & 31;
            sH[li * SHL + b * SHS + 64 + f] =
                __float2half(g_xT[(t * NL + l0 + li) * 128 + f * 32 + b]);
        }
        if (t > 0) {
            const float* hm = g_h[cur] + lm * 2048;
            const float* hp = g_h[cur] + lp * 2048;
#pragma unroll
            for (int kr = 0; kr < 2; kr++) {
                int k = kr ? k1 : k0;
#pragma unroll
                for (int nt = 0; nt < 4; nt++) {
                    int b = nt * 8 + bq;
                    float2 m0 = __ldcg((const float2*)&hm[k * 32 + b]);
                    float2 p1 = __ldcg((const float2*)&hp[k * 32 + b]);
                    float2 h0 = o[0][kr][nt], h1 = o[1][kr][nt];
                    float sx0 = amc[0] * m0.x + a0c[0] * h0.x + apc[0] * h1.x;
                    float sy0 = amc[0] * m0.y + a0c[0] * h0.y + apc[0] * h1.y;
                    float sx1 = amc[1] * h0.x + a0c[1] * h1.x + apc[1] * p1.x;
                    float sy1 = amc[1] * h0.y + a0c[1] * h1.y + apc[1] * p1.y;
                    sH[0 * SHL + b * SHS + k]       = __float2half(sx0);
                    sH[0 * SHL + (b + 1) * SHS + k] = __float2half(sy0);
                    sH[1 * SHL + b * SHS + k]       = __float2half(sx1);
                    sH[1 * SHL + (b + 1) * SHS + k] = __float2half(sy1);
                }
            }
        }
        __syncthreads();

        // ---- Phase B: MMA + epilogue, per link ----
#pragma unroll 1
        for (int li = 0; li < 2; li++) {
            const int l = l0 + li;
            const __half* sHl = sH + li * SHL;
            const uint4* wbase = (const uint4*)g_wf + (uint32_t)((l * 4 + warp) * 15) * 32 + lane;
            float bn0 = b_nh[k0 * NL + l], bn1 = b_nh[k1 * NL + l];   // L1-cached, immutable

            float2 dR[2][4], dZ[2][4], dN[2][4], xiN[2][4];
#pragma unroll
            for (int nt = 0; nt < 4; nt++) {
                dR[0][nt] = make_float2(0, 0);      dR[1][nt] = make_float2(0, 0);
                dZ[0][nt] = make_float2(0, 0);      dZ[1][nt] = make_float2(0, 0);
                dN[0][nt] = make_float2(bn0, bn0);  dN[1][nt] = make_float2(bn1, bn1);
                xiN[0][nt] = make_float2(0, 0);     xiN[1][nt] = make_float2(0, 0);
            }

            if (t > 0) {
#pragma unroll
                for (int kit = 0; kit < 4; kit++) {
                    uint4 Ar = wbase[(kit * 3 + 0) * 32];
                    uint4 Au = wbase[(kit * 3 + 1) * 32];
                    uint4 An = wbase[(kit * 3 + 2) * 32];
                    const int hb = kit * 16 + bq;
#pragma unroll
                    for (int nt = 0; nt < 4; nt++) {
                        int bb = nt * 8 + gr;
                        uint32_t b0 = *(const uint32_t*)&sHl[bb * SHS + hb];
                        uint32_t b1 = *(const uint32_t*)&sHl[bb * SHS + hb + 8];
                        mma16816(dR[0][nt], dR[1][nt], Ar, b0, b1);
                        mma16816(dZ[0][nt], dZ[1][nt], Au, b0, b1);
                        mma16816(dN[0][nt], dN[1][nt], An, b0, b1);
                    }
                }
            }
            {   // kit 4: x-weights + biases (R, Z -> dR,dZ ; Nx -> xiN)
                uint4 Ar = wbase[(12 + 0) * 32];
                uint4 Au = wbase[(12 + 1) * 32];
                uint4 Ax = wbase[(12 + 2) * 32];
                const int hb = 64 + bq;
#pragma unroll
                for (int nt = 0; nt < 4; nt++) {
                    int bb = nt * 8 + gr;
                    uint32_t b0 = *(const uint32_t*)&sHl[bb * SHS + hb];
                    uint32_t b1 = *(const uint32_t*)&sHl[bb * SHS + hb + 8];
                    mma16816(dR[0][nt], dR[1][nt], Ar, b0, b1);
                    mma16816(dZ[0][nt], dZ[1][nt], Au, b0, b1);
                    mma16816(xiN[0][nt], xiN[1][nt], Ax, b0, b1);
                }
            }

            // epilogue: gates, update register h, write-through to gmem for neighbors
            float* hn = g_h[nxt] + l * 2048;
#pragma unroll
            for (int kr = 0; kr < 2; kr++) {
                int k = kr ? k1 : k0;
#pragma unroll
                for (int nt = 0; nt < 4; nt++) {
                    int b = nt * 8 + bq;
                    float2 hold = o[li][kr][nt];
                    float r0 = fsigmoid(dR[kr][nt].x), r1 = fsigmoid(dR[kr][nt].y);
                    float z0 = fsigmoid(dZ[kr][nt].x), z1 = fsigmoid(dZ[kr][nt].y);
                    float n0 = ftanh_fast(xiN[kr][nt].x + r0 * dN[kr][nt].x);
                    float n1 = ftanh_fast(xiN[kr][nt].y + r1 * dN[kr][nt].y);
                    float2 nw = make_float2(n0 + z0 * (hold.x - n0),
                                            n1 + z1 * (hold.y - n1));
                    o[li][kr][nt] = nw;
                    *(float2*)&hn[k * 32 + b] = nw;
                }
            }
        }

        // ---- wavefront neighbor sync ----
        if (t < NT - 1) {
            __threadfence();
            __syncthreads();
            if (tid == 0) {
                *(volatile int*)&g_flag[c * 32] = t + 1;
                if (c > 0)
                    while (*(volatile int*)&g_flag[(c - 1) * 32] <= t) __nanosleep(64);
                if (c < NC - 1)
                    while (*(volatile int*)&g_flag[(c + 1) * 32] <= t) __nanosleep(64);
            }
            __syncthreads();
        }
    }

    // ---- fc head (own links; final h in g_h[0] after t=11) ----
    __syncthreads();
    if (tid < 64) {
        int li = tid >> 5, b = tid & 31;
        int l = l0 + li;
        const float* h = g_h[0] + l * 2048;
        float acc = b_fc[l];
#pragma unroll 8
        for (int k = 0; k < NH; k++) acc += __ldcg(&h[k * 32 + b]) * w_fc[l * NH + k];
        out[b * NL + l] = acc;
    }
}

// ---------------- launch ----------------
extern "C" void kernel_launch(void* const* d_in, const int* in_sizes, int n_in,
                              void* d_out, int out_size) {
    const float* x    = (const float*)d_in[0];
    const float* att  = (const float*)d_in[1];
    const float* w_rh = (const float*)d_in[2];
    const float* b_rh = (const float*)d_in[3];
    const float* w_ri = (const float*)d_in[4];
    const float* b_ri = (const float*)d_in[5];
    const float* w_uh = (const float*)d_in[6];
    const float* b_uh = (const float*)d_in[7];
    const float* w_ui = (const float*)d_in[8];
    const float* b_ui = (const float*)d_in[9];
    const float* w_nh = (const float*)d_in[10];
    const float* b_nh = (const float*)d_in[11];
    const float* w_ni = (const float*)d_in[12];
    const float* b_ni = (const float*)d_in[13];
    const float* w_fc = (const float*)d_in[14];
    const float* b_fc = (const float*)d_in[15];

    prep_x<<<6144, 256>>>(x);
    prep_wfrag_h<<<3072, 256>>>(w_rh, w_uh, w_nh);
    prep_wfrag_x<<<3072, 128>>>(w_ri, w_ui, w_ni, b_rh, b_ri, b_uh, b_ui, b_ni);

    fused_kernel<<<NC, 128>>>(att, b_nh, w_fc, b_fc, (float*)d_out);
}

// round 12
// speedup vs baseline: 2.5970x; 1.0868x over previous
#include <cuda_runtime.h>
#include <cuda_fp16.h>
#include <cstdint>

#define NL 1024
#define NB 32
#define NT 12
#define NF 4
#define NH 64
#define NC 512          // CTAs, 2 links each
#define SHS 88          // sH row stride in halfs (per batch row)
#define SHL (32 * SHS)  // per-link sH halfs

// Scratch (static device globals: allocation-free rule)
__device__ float g_h[2][NL * NH * NB];      // hidden [L][H][B], double buffered (neighbor exchange)
__device__ float g_xT[NT * NL * NF * NB];   // x transposed to [T][L][F][B]
__device__ __half g_wf[NL * 4 * 15 * 256];  // A-fragments: ((l*4+warp)*15 + kit*3 + gate) blocks of 256 half
__device__ int g_flag[NC * 32];             // per-CTA progress flags, 128B stride

// packed f32x2 FMA
__device__ __forceinline__ float2 ffma2(float2 a, float2 b, float2 c) {
    unsigned long long ua = *reinterpret_cast<unsigned long long*>(&a);
    unsigned long long ub = *reinterpret_cast<unsigned long long*>(&b);
    unsigned long long uc = *reinterpret_cast<unsigned long long*>(&c);
    unsigned long long ud;
    asm("fma.rn.f32x2 %0, %1, %2, %3;" : "=l"(ud) : "l"(ua), "l"(ub), "l"(uc));
    return *reinterpret_cast<float2*>(&ud);
}

// D(16x8,f32) += A(16x16,f16) @ B(16x8,f16)
__device__ __forceinline__ void mma16816(float2& d01, float2& d23,
                                         uint4 a, uint32_t b0, uint32_t b1) {
    asm volatile(
        "mma.sync.aligned.m16n8k16.row.col.f32.f16.f16.f32 "
        "{%0,%1,%2,%3}, {%4,%5,%6,%7}, {%8,%9}, {%0,%1,%2,%3};"
        : "+f"(d01.x), "+f"(d01.y), "+f"(d23.x), "+f"(d23.y)
        : "r"(a.x), "r"(a.y), "r"(a.z), "r"(a.w), "r"(b0), "r"(b1));
}

// HW tanh: single MUFU op (sm_75+), vs EX2+RCP chains
__device__ __forceinline__ float tanh_hw(float x) {
    float y;
    asm("tanh.approx.f32 %0, %1;" : "=f"(y) : "f"(x));
    return y;
}
__device__ __forceinline__ float sigmoid_hw(float x) {
    return fmaf(0.5f, tanh_hw(0.5f * x), 0.5f);
}

// ---------------- prep kernels ----------------

__global__ void prep_x(const float* __restrict__ x) {
    int idx = blockIdx.x * blockDim.x + threadIdx.x;
    if (idx < NC * 32) g_flag[idx] = 0;          // reset wavefront flags each replay
    if (idx >= NT * NL * NF * NB) return;
    int b = idx & 31;
    int f = (idx >> 5) & 3;
    int l = (idx >> 7) & 1023;
    int t = idx >> 17;
    g_xT[idx] = x[((b * NT + t) * NF + f) * NL + l];
}

// hidden-gate weights -> A-fragments (kits 0..3), smem-staged for coalescing.
__global__ void prep_wfrag_h(const float* __restrict__ w_rh, const float* __restrict__ w_uh,
                             const float* __restrict__ w_nh) {
    __shared__ float sm[4096];
    int bid = blockIdx.x;                // l*3 + gate
    int gate = bid % 3, l = bid / 3;
    int tid = threadIdx.x;               // 256
    const float* W = (gate == 0) ? w_rh : (gate == 1) ? w_uh : w_nh;
    const float4* src = (const float4*)(W + l * 4096);
    float4* dsm = (float4*)sm;
#pragma unroll
    for (int i = 0; i < 4; i++) dsm[tid + i * 256] = src[tid + i * 256];
    __syncthreads();
#pragma unroll
    for (int i = 0; i < 2; i++) {
        int e = tid + i * 256;           // 0..511
        int fb = e >> 5;                 // 0..15 : kit*4 + wm
        int kit = fb >> 2, wm = fb & 3;
        int lane = e & 31, gr = lane >> 2, tig = lane & 3;
        uint32_t v[4];
#pragma unroll
        for (int s = 0; s < 4; s++) {
            int row = wm * 16 + gr + ((s & 1) ? 8 : 0);       // gru output k
            int col = kit * 16 + tig * 2 + ((s & 2) ? 8 : 0); // h input
            __half2 h = __floats2half2_rn(sm[col * 64 + row], sm[(col + 1) * 64 + row]);
            v[s] = *(uint32_t*)&h;
        }
        ((uint4*)g_wf)[((l * 4 + wm) * 15 + kit * 3 + gate) * 32 + lane] =
            make_uint4(v[0], v[1], v[2], v[3]);
    }
}

// x-weights + biases -> A-fragments (kit 4).
__global__ void prep_wfrag_x(const float* __restrict__ w_ri, const float* __restrict__ w_ui,
                             const float* __restrict__ w_ni,
                             const float* __restrict__ b_rh, const float* __restrict__ b_ri,
                             const float* __restrict__ b_uh, const float* __restrict__ b_ui,
                             const float* __restrict__ b_ni) {
    int bid = blockIdx.x;                // l*3 + gate
    int gate = bid % 3, l = bid / 3;
    int tid = threadIdx.x;               // 128
    int wm = tid >> 5, lane = tid & 31, gr = lane >> 2, tig = lane & 3;
    const float* Wx = (gate == 0) ? w_ri : (gate == 1) ? w_ui : w_ni;
    uint32_t v[4];
#pragma unroll
    for (int s = 0; s < 4; s++) {
        int row = wm * 16 + gr + ((s & 1) ? 8 : 0);
        int cb = 64 + tig * 2 + ((s & 2) ? 8 : 0);
        float f[2];
#pragma unroll
        for (int j = 0; j < 2; j++) {
            int cc = cb + j;
            float val = 0.0f;
            if (cc < 68) {
                val = Wx[l * 256 + (cc - 64) * 64 + row];
            } else if (cc == 68) {
                if (gate == 0)      val = b_rh[row * NL + l] + b_ri[row * NL + l];
                else if (gate == 1) val = b_uh[row * NL + l] + b_ui[row * NL + l];
                else                val = b_ni[row * NL + l];
            }
            f[j] = val;
        }
        __half2 h = __floats2half2_rn(f[0], f[1]);
        v[s] = *(uint32_t*)&h;
    }
    ((uint4*)g_wf)[((l * 4 + wm) * 15 + 12 + gate) * 32 + lane] =
        make_uint4(v[0], v[1], v[2], v[3]);
}

// ---------------- fused persistent GRU kernel ----------------
// CTA c owns links {2c, 2c+1}; own h(t) lives in registers. Halo links via L2.
// x-GEMM + biases folded into MMA kit4. Gates via HW tanh (1 MUFU each).
// Wavefront sync via per-CTA flags; 512 CTAs co-resident (4/SM * 148 = 592).

__global__ void __launch_bounds__(128, 4)
fused_kernel(const float* __restrict__ att, const float* __restrict__ b_nh,
             const float* __restrict__ w_fc, const float* __restrict__ b_fc,
             float* __restrict__ out) {
    __shared__ __half sH[2 * SHL];   // per-link B operand: [b][88] halfs

    const int c = blockIdx.x, tid = threadIdx.x;
    const int lane = tid & 31, warp = tid >> 5;
    const int gr = lane >> 2, tig = lane & 3;
    const int k0 = warp * 16 + gr, k1 = k0 + 8;
    const int bq = tig * 2;
    const int l0 = 2 * c;

    // constant sH rows: row 68 = 1.0 (bias), rows 69..79 = 0 (written once)
    for (int e = tid; e < 2 * 32 * 12; e += 128) {
        int li = e / 384, rem = e % 384;
        int b = rem / 12, row = 68 + rem % 12;
        sH[li * SHL + b * SHS + row] = (row == 68) ? __float2half(1.0f) : __half(0);
    }

    // hoisted per-link invariants: attention coeffs + b_nh
    float a0c[2], amc[2], apc[2], bnh[2][2];
#pragma unroll
    for (int li = 0; li < 2; li++) {
        int l = l0 + li;
        a0c[li] = att[l * NL + l];
        amc[li] = (l > 0)      ? att[l * NL + l - 1] : 0.0f;
        apc[li] = (l < NL - 1) ? att[l * NL + l + 1] : 0.0f;
        bnh[li][0] = b_nh[k0 * NL + l];
        bnh[li][1] = b_nh[k1 * NL + l];
    }
    const int lm = (l0 > 0) ? l0 - 1 : l0;           // left halo (coeff 0 at edge)
    const int lp = (l0 + 2 < NL) ? l0 + 2 : l0 + 1;  // right halo (coeff 0 at edge)

    // own hidden state in registers: o[li][kreg][nt] = h[l0+li][k][b..b+1]
    float2 o[2][2][4];
#pragma unroll
    for (int li = 0; li < 2; li++)
#pragma unroll
        for (int kr = 0; kr < 2; kr++)
#pragma unroll
            for (int nt = 0; nt < 4; nt++) o[li][kr][nt] = make_float2(0.0f, 0.0f);

    for (int t = 0; t < NT; t++) {
        const int cur = t & 1, nxt = cur ^ 1;

        // ---- Phase A: write sH (x rows every step; hatt rows for t>0) ----
#pragma unroll
        for (int i = 0; i < 2; i++) {
            int e = tid + i * 128;
            int li = e >> 7, f = (e >> 5) & 3, b = e & 31;
            sH[li * SHL + b * SHS + 64 + f] =
                __float2half(g_xT[(t * NL + l0 + li) * 128 + f * 32 + b]);
        }
        if (t > 0) {
            const float* hm = g_h[cur] + lm * 2048;
            const float* hp = g_h[cur] + lp * 2048;
#pragma unroll
            for (int kr = 0; kr < 2; kr++) {
                int k = kr ? k1 : k0;
#pragma unroll
                for (int nt = 0; nt < 4; nt++) {
                    int b = nt * 8 + bq;
                    float2 m0 = __ldcg((const float2*)&hm[k * 32 + b]);
                    float2 p1 = __ldcg((const float2*)&hp[k * 32 + b]);
                    float2 h0 = o[0][kr][nt], h1 = o[1][kr][nt];
                    float sx0 = amc[0] * m0.x + a0c[0] * h0.x + apc[0] * h1.x;
                    float sy0 = amc[0] * m0.y + a0c[0] * h0.y + apc[0] * h1.y;
                    float sx1 = amc[1] * h0.x + a0c[1] * h1.x + apc[1] * p1.x;
                    float sy1 = amc[1] * h0.y + a0c[1] * h1.y + apc[1] * p1.y;
                    sH[0 * SHL + b * SHS + k]       = __float2half(sx0);
                    sH[0 * SHL + (b + 1) * SHS + k] = __float2half(sy0);
                    sH[1 * SHL + b * SHS + k]       = __float2half(sx1);
                    sH[1 * SHL + (b + 1) * SHS + k] = __float2half(sy1);
                }
            }
        }
        __syncthreads();

        // ---- Phase B: MMA + epilogue, per link ----
#pragma unroll 1
        for (int li = 0; li < 2; li++) {
            const int l = l0 + li;
            const __half* sHl = sH + li * SHL;
            const uint4* wbase = (const uint4*)g_wf + (uint32_t)((l * 4 + warp) * 15) * 32 + lane;
            const float bn0 = bnh[li][0], bn1 = bnh[li][1];

            float2 dR[2][4], dZ[2][4], dN[2][4], xiN[2][4];
#pragma unroll
            for (int nt = 0; nt < 4; nt++) {
                dR[0][nt] = make_float2(0, 0);      dR[1][nt] = make_float2(0, 0);
                dZ[0][nt] = make_float2(0, 0);      dZ[1][nt] = make_float2(0, 0);
                dN[0][nt] = make_float2(bn0, bn0);  dN[1][nt] = make_float2(bn1, bn1);
                xiN[0][nt] = make_float2(0, 0);     xiN[1][nt] = make_float2(0, 0);
            }

            if (t > 0) {
#pragma unroll
                for (int kit = 0; kit < 4; kit++) {
                    uint4 Ar = wbase[(kit * 3 + 0) * 32];
                    uint4 Au = wbase[(kit * 3 + 1) * 32];
                    uint4 An = wbase[(kit * 3 + 2) * 32];
                    const int hb = kit * 16 + bq;
#pragma unroll
                    for (int nt = 0; nt < 4; nt++) {
                        int bb = nt * 8 + gr;
                        uint32_t b0 = *(const uint32_t*)&sHl[bb * SHS + hb];
                        uint32_t b1 = *(const uint32_t*)&sHl[bb * SHS + hb + 8];
                        mma16816(dR[0][nt], dR[1][nt], Ar, b0, b1);
                        mma16816(dZ[0][nt], dZ[1][nt], Au, b0, b1);
                        mma16816(dN[0][nt], dN[1][nt], An, b0, b1);
                    }
                }
            }
            {   // kit 4: x-weights + biases (R, Z -> dR,dZ ; Nx -> xiN)
                uint4 Ar = wbase[(12 + 0) * 32];
                uint4 Au = wbase[(12 + 1) * 32];
                uint4 Ax = wbase[(12 + 2) * 32];
                const int hb = 64 + bq;
#pragma unroll
                for (int nt = 0; nt < 4; nt++) {
                    int bb = nt * 8 + gr;
                    uint32_t b0 = *(const uint32_t*)&sHl[bb * SHS + hb];
                    uint32_t b1 = *(const uint32_t*)&sHl[bb * SHS + hb + 8];
                    mma16816(dR[0][nt], dR[1][nt], Ar, b0, b1);
                    mma16816(dZ[0][nt], dZ[1][nt], Au, b0, b1);
                    mma16816(xiN[0][nt], xiN[1][nt], Ax, b0, b1);
                }
            }

            // epilogue: gates via HW tanh, update register h, write-through for neighbors
            float* hn = g_h[nxt] + l * 2048;
#pragma unroll
            for (int kr = 0; kr < 2; kr++) {
                int k = kr ? k1 : k0;
#pragma unroll
                for (int nt = 0; nt < 4; nt++) {
                    int b = nt * 8 + bq;
                    float2 hold = o[li][kr][nt];
                    float r0 = sigmoid_hw(dR[kr][nt].x), r1 = sigmoid_hw(dR[kr][nt].y);
                    float z0 = sigmoid_hw(dZ[kr][nt].x), z1 = sigmoid_hw(dZ[kr][nt].y);
                    float n0 = tanh_hw(fmaf(r0, dN[kr][nt].x, xiN[kr][nt].x));
                    float n1 = tanh_hw(fmaf(r1, dN[kr][nt].y, xiN[kr][nt].y));
                    float2 nw = make_float2(n0 + z0 * (hold.x - n0),
                                            n1 + z1 * (hold.y - n1));
                    o[li][kr][nt] = nw;
                    *(float2*)&hn[k * 32 + b] = nw;
                }
            }
        }

        // ---- wavefront neighbor sync ----
        if (t < NT - 1) {
            __threadfence();
            __syncthreads();
            if (tid == 0) {
                *(volatile int*)&g_flag[c * 32] = t + 1;
                if (c > 0)
                    while (*(volatile int*)&g_flag[(c - 1) * 32] <= t) __nanosleep(64);
                if (c < NC - 1)
                    while (*(volatile int*)&g_flag[(c + 1) * 32] <= t) __nanosleep(64);
            }
            __syncthreads();
        }
    }

    // ---- fc head (own links; final h in g_h[0] after t=11) ----
    __syncthreads();
    if (tid < 64) {
        int li = tid >> 5, b = tid & 31;
        int l = l0 + li;
        const float* h = g_h[0] + l * 2048;
        float acc = b_fc[l];
#pragma unroll 8
        for (int k = 0; k < NH; k++) acc += __ldcg(&h[k * 32 + b]) * w_fc[l * NH + k];
        out[b * NL + l] = acc;
    }
}

// ---------------- launch ----------------
extern "C" void kernel_launch(void* const* d_in, const int* in_sizes, int n_in,
                              void* d_out, int out_size) {
    const float* x    = (const float*)d_in[0];
    const float* att  = (const float*)d_in[1];
    const float* w_rh = (const float*)d_in[2];
    const float* b_rh = (const float*)d_in[3];
    const float* w_ri = (const float*)d_in[4];
    const float* b_ri = (const float*)d_in[5];
    const float* w_uh = (const float*)d_in[6];
    const float* b_uh = (const float*)d_in[7];
    const float* w_ui = (const float*)d_in[8];
    const float* b_ui = (const float*)d_in[9];
    const float* w_nh = (const float*)d_in[10];
    const float* b_nh = (const float*)d_in[11];
    const float* w_ni = (const float*)d_in[12];
    const float* b_ni = (const float*)d_in[13];
    const float* w_fc = (const float*)d_in[14];
    const float* b_fc = (const float*)d_in[15];

    prep_x<<<6144, 256>>>(x);
    prep_wfrag_h<<<3072, 256>>>(w_rh, w_uh, w_nh);
    prep_wfrag_x<<<3072, 128>>>(w_ri, w_ui, w_ni, b_rh, b_ri, b_uh, b_ui, b_ni);

    fused_kernel<<<NC, 128>>>(att, b_nh, w_fc, b_fc, (float*)d_out);
}

// round 13
// speedup vs baseline: 2.6808x; 1.0323x over previous
#include <cuda_runtime.h>
#include <cuda_fp16.h>
#include <cstdint>

#define NL 1024
#define NB 32
#define NT 12
#define NF 4
#define NH 64
#define NC 512          // CTAs, 2 links each
#define SHS 88          // sH row stride in halfs (per batch row)
#define SHL (32 * SHS)  // per-link sH halfs

// Scratch (static device globals: allocation-free rule)
__device__ float g_h[2][NL * NH * NB];      // hidden [L][H][B], double buffered (neighbor exchange)
__device__ float g_xT[NT * NL * NF * NB];   // x transposed to [T][L][F][B]
__device__ __half g_wf[NL * 4 * 15 * 256];  // A-fragments: ((l*4+warp)*15 + kit*3 + gate) blocks of 256 half
__device__ int g_flag[NC * 32];             // per-CTA progress flags, 128B stride

// D(16x8,f32) += A(16x16,f16) @ B(16x8,f16)
__device__ __forceinline__ void mma16816(float2& d01, float2& d23,
                                         uint4 a, uint32_t b0, uint32_t b1) {
    asm volatile(
        "mma.sync.aligned.m16n8k16.row.col.f32.f16.f16.f32 "
        "{%0,%1,%2,%3}, {%4,%5,%6,%7}, {%8,%9}, {%0,%1,%2,%3};"
        : "+f"(d01.x), "+f"(d01.y), "+f"(d23.x), "+f"(d23.y)
        : "r"(a.x), "r"(a.y), "r"(a.z), "r"(a.w), "r"(b0), "r"(b1));
}

// HW tanh: single MUFU op
__device__ __forceinline__ float tanh_hw(float x) {
    float y;
    asm("tanh.approx.f32 %0, %1;" : "=f"(y) : "f"(x));
    return y;
}
__device__ __forceinline__ float sigmoid_hw(float x) {
    return fmaf(0.5f, tanh_hw(0.5f * x), 0.5f);
}

// release/acquire flag ops (CG grid-sync pattern; replaces __threadfence)
__device__ __forceinline__ void flag_release(int* p, int v) {
    asm volatile("st.release.gpu.global.s32 [%0], %1;" :: "l"(p), "r"(v) : "memory");
}
__device__ __forceinline__ int flag_acquire(const int* p) {
    int v;
    asm volatile("ld.acquire.gpu.global.s32 %0, [%1];" : "=r"(v) : "l"(p) : "memory");
    return v;
}

// ---------------- prep kernels ----------------

__global__ void prep_x(const float* __restrict__ x) {
    int idx = blockIdx.x * blockDim.x + threadIdx.x;
    if (idx < NC * 32) g_flag[idx] = 0;          // reset wavefront flags each replay
    if (idx >= NT * NL * NF * NB) return;
    int b = idx & 31;
    int f = (idx >> 5) & 3;
    int l = (idx >> 7) & 1023;
    int t = idx >> 17;
    g_xT[idx] = x[((b * NT + t) * NF + f) * NL + l];
}

// hidden-gate weights -> A-fragments (kits 0..3), smem-staged for coalescing.
__global__ void prep_wfrag_h(const float* __restrict__ w_rh, const float* __restrict__ w_uh,
                             const float* __restrict__ w_nh) {
    __shared__ float sm[4096];
    int bid = blockIdx.x;                // l*3 + gate
    int gate = bid % 3, l = bid / 3;
    int tid = threadIdx.x;               // 256
    const float* W = (gate == 0) ? w_rh : (gate == 1) ? w_uh : w_nh;
    const float4* src = (const float4*)(W + l * 4096);
    float4* dsm = (float4*)sm;
#pragma unroll
    for (int i = 0; i < 4; i++) dsm[tid + i * 256] = src[tid + i * 256];
    __syncthreads();
#pragma unroll
    for (int i = 0; i < 2; i++) {
        int e = tid + i * 256;           // 0..511
        int fb = e >> 5;                 // 0..15 : kit*4 + wm
        int kit = fb >> 2, wm = fb & 3;
        int lane = e & 31, gr = lane >> 2, tig = lane & 3;
        uint32_t v[4];
#pragma unroll
        for (int s = 0; s < 4; s++) {
            int row = wm * 16 + gr + ((s & 1) ? 8 : 0);       // gru output k
            int col = kit * 16 + tig * 2 + ((s & 2) ? 8 : 0); // h input
            __half2 h = __floats2half2_rn(sm[col * 64 + row], sm[(col + 1) * 64 + row]);
            v[s] = *(uint32_t*)&h;
        }
        ((uint4*)g_wf)[((l * 4 + wm) * 15 + kit * 3 + gate) * 32 + lane] =
            make_uint4(v[0], v[1], v[2], v[3]);
    }
}

// x-weights + biases -> A-fragments (kit 4).
__global__ void prep_wfrag_x(const float* __restrict__ w_ri, const float* __restrict__ w_ui,
                             const float* __restrict__ w_ni,
                             const float* __restrict__ b_rh, const float* __restrict__ b_ri,
                             const float* __restrict__ b_uh, const float* __restrict__ b_ui,
                             const float* __restrict__ b_ni) {
    int bid = blockIdx.x;                // l*3 + gate
    int gate = bid % 3, l = bid / 3;
    int tid = threadIdx.x;               // 128
    int wm = tid >> 5, lane = tid & 31, gr = lane >> 2, tig = lane & 3;
    const float* Wx = (gate == 0) ? w_ri : (gate == 1) ? w_ui : w_ni;
    uint32_t v[4];
#pragma unroll
    for (int s = 0; s < 4; s++) {
        int row = wm * 16 + gr + ((s & 1) ? 8 : 0);
        int cb = 64 + tig * 2 + ((s & 2) ? 8 : 0);
        float f[2];
#pragma unroll
        for (int j = 0; j < 2; j++) {
            int cc = cb + j;
            float val = 0.0f;
            if (cc < 68) {
                val = Wx[l * 256 + (cc - 64) * 64 + row];
            } else if (cc == 68) {
                if (gate == 0)      val = b_rh[row * NL + l] + b_ri[row * NL + l];
                else if (gate == 1) val = b_uh[row * NL + l] + b_ui[row * NL + l];
                else                val = b_ni[row * NL + l];
            }
            f[j] = val;
        }
        __half2 h = __floats2half2_rn(f[0], f[1]);
        v[s] = *(uint32_t*)&h;
    }
    ((uint4*)g_wf)[((l * 4 + wm) * 15 + 12 + gate) * 32 + lane] =
        make_uint4(v[0], v[1], v[2], v[3]);
}

// ---------------- fused persistent GRU kernel ----------------
// CTA c owns links {2c, 2c+1}; own h(t) lives in registers. Halo links via L2.
// x-GEMM + biases folded into MMA kit4. Gates via HW tanh.
// Wavefront handshake: st.release flag / per-warp ld.acquire spin (no MEMBAR,
// no trailing block barrier); x-staging for t+1 overlaps the spin.

__global__ void __launch_bounds__(128, 4)
fused_kernel(const float* __restrict__ att, const float* __restrict__ b_nh,
             const float* __restrict__ w_fc, const float* __restrict__ b_fc,
             float* __restrict__ out) {
    __shared__ __half sH[2 * SHL];   // per-link B operand: [b][88] halfs

    const int c = blockIdx.x, tid = threadIdx.x;
    const int lane = tid & 31, warp = tid >> 5;
    const int gr = lane >> 2, tig = lane & 3;
    const int k0 = warp * 16 + gr, k1 = k0 + 8;
    const int bq = tig * 2;
    const int l0 = 2 * c;

    // constant sH rows: row 68 = 1.0 (bias), rows 69..79 = 0 (written once)
    for (int e = tid; e < 2 * 32 * 12; e += 128) {
        int li = e / 384, rem = e % 384;
        int b = rem / 12, row = 68 + rem % 12;
        sH[li * SHL + b * SHS + row] = (row == 68) ? __float2half(1.0f) : __half(0);
    }

    // hoisted per-link invariants: attention coeffs + b_nh
    float a0c[2], amc[2], apc[2], bnh[2][2];
#pragma unroll
    for (int li = 0; li < 2; li++) {
        int l = l0 + li;
        a0c[li] = att[l * NL + l];
        amc[li] = (l > 0)      ? att[l * NL + l - 1] : 0.0f;
        apc[li] = (l < NL - 1) ? att[l * NL + l + 1] : 0.0f;
        bnh[li][0] = b_nh[k0 * NL + l];
        bnh[li][1] = b_nh[k1 * NL + l];
    }
    const int lm = (l0 > 0) ? l0 - 1 : l0;           // left halo (coeff 0 at edge)
    const int lp = (l0 + 2 < NL) ? l0 + 2 : l0 + 1;  // right halo (coeff 0 at edge)

    // own hidden state in registers
    float2 o[2][2][4];
#pragma unroll
    for (int li = 0; li < 2; li++)
#pragma unroll
        for (int kr = 0; kr < 2; kr++)
#pragma unroll
            for (int nt = 0; nt < 4; nt++) o[li][kr][nt] = make_float2(0.0f, 0.0f);

    // x staging for step tt -> sH rows 64..67 (no neighbor dependence)
    auto stage_x = [&](int tt) {
#pragma unroll
        for (int i = 0; i < 2; i++) {
            int e = tid + i * 128;
            int li = e >> 7, f = (e >> 5) & 3, b = e & 31;
            sH[li * SHL + b * SHS + 64 + f] =
                __float2half(g_xT[(tt * NL + l0 + li) * 128 + f * 32 + b]);
        }
    };

    stage_x(0);   // t=0 rows; made visible by the pre-phase-B __syncthreads

    for (int t = 0; t < NT; t++) {
        const int cur = t & 1, nxt = cur ^ 1;

        // ---- Phase A (t>0): hatt rows; warp proceeds as soon as its spin finished ----
        if (t > 0) {
            const float* hm = g_h[cur] + lm * 2048;
            const float* hp = g_h[cur] + lp * 2048;
#pragma unroll
            for (int kr = 0; kr < 2; kr++) {
                int k = kr ? k1 : k0;
#pragma unroll
                for (int nt = 0; nt < 4; nt++) {
                    int b = nt * 8 + bq;
                    float2 m0 = __ldcg((const float2*)&hm[k * 32 + b]);
                    float2 p1 = __ldcg((const float2*)&hp[k * 32 + b]);
                    float2 h0 = o[0][kr][nt], h1 = o[1][kr][nt];
                    float sx0 = amc[0] * m0.x + a0c[0] * h0.x + apc[0] * h1.x;
                    float sy0 = amc[0] * m0.y + a0c[0] * h0.y + apc[0] * h1.y;
                    float sx1 = amc[1] * h0.x + a0c[1] * h1.x + apc[1] * p1.x;
                    float sy1 = amc[1] * h0.y + a0c[1] * h1.y + apc[1] * p1.y;
                    sH[0 * SHL + b * SHS + k]       = __float2half(sx0);
                    sH[0 * SHL + (b + 1) * SHS + k] = __float2half(sy0);
                    sH[1 * SHL + b * SHS + k]       = __float2half(sx1);
                    sH[1 * SHL + (b + 1) * SHS + k] = __float2half(sy1);
                }
            }
        }
        __syncthreads();   // sH (x + hatt) visible to all warps

        // ---- Phase B: MMA + epilogue, per link ----
#pragma unroll 1
        for (int li = 0; li < 2; li++) {
            const int l = l0 + li;
            const __half* sHl = sH + li * SHL;
            const uint4* wbase = (const uint4*)g_wf + (uint32_t)((l * 4 + warp) * 15) * 32 + lane;
            const float bn0 = bnh[li][0], bn1 = bnh[li][1];

            float2 dR[2][4], dZ[2][4], dN[2][4], xiN[2][4];
#pragma unroll
            for (int nt = 0; nt < 4; nt++) {
                dR[0][nt] = make_float2(0, 0);      dR[1][nt] = make_float2(0, 0);
                dZ[0][nt] = make_float2(0, 0);      dZ[1][nt] = make_float2(0, 0);
                dN[0][nt] = make_float2(bn0, bn0);  dN[1][nt] = make_float2(bn1, bn1);
                xiN[0][nt] = make_float2(0, 0);     xiN[1][nt] = make_float2(0, 0);
            }

            if (t > 0) {
#pragma unroll
                for (int kit = 0; kit < 4; kit++) {
                    uint4 Ar = wbase[(kit * 3 + 0) * 32];
                    uint4 Au = wbase[(kit * 3 + 1) * 32];
                    uint4 An = wbase[(kit * 3 + 2) * 32];
                    const int hb = kit * 16 + bq;
#pragma unroll
                    for (int nt = 0; nt < 4; nt++) {
                        int bb = nt * 8 + gr;
                        uint32_t b0 = *(const uint32_t*)&sHl[bb * SHS + hb];
                        uint32_t b1 = *(const uint32_t*)&sHl[bb * SHS + hb + 8];
                        mma16816(dR[0][nt], dR[1][nt], Ar, b0, b1);
                        mma16816(dZ[0][nt], dZ[1][nt], Au, b0, b1);
                        mma16816(dN[0][nt], dN[1][nt], An, b0, b1);
                    }
                }
            }
            {   // kit 4: x-weights + biases
                uint4 Ar = wbase[(12 + 0) * 32];
                uint4 Au = wbase[(12 + 1) * 32];
                uint4 Ax = wbase[(12 + 2) * 32];
                const int hb = 64 + bq;
#pragma unroll
                for (int nt = 0; nt < 4; nt++) {
                    int bb = nt * 8 + gr;
                    uint32_t b0 = *(const uint32_t*)&sHl[bb * SHS + hb];
                    uint32_t b1 = *(const uint32_t*)&sHl[bb * SHS + hb + 8];
                    mma16816(dR[0][nt], dR[1][nt], Ar, b0, b1);
                    mma16816(dZ[0][nt], dZ[1][nt], Au, b0, b1);
                    mma16816(xiN[0][nt], xiN[1][nt], Ax, b0, b1);
                }
            }

            // epilogue: gates via HW tanh, update register h, write-through for neighbors
            float* hn = g_h[nxt] + l * 2048;
#pragma unroll
            for (int kr = 0; kr < 2; kr++) {
                int k = kr ? k1 : k0;
#pragma unroll
                for (int nt = 0; nt < 4; nt++) {
                    int b = nt * 8 + bq;
                    float2 hold = o[li][kr][nt];
                    float r0 = sigmoid_hw(dR[kr][nt].x), r1 = sigmoid_hw(dR[kr][nt].y);
                    float z0 = sigmoid_hw(dZ[kr][nt].x), z1 = sigmoid_hw(dZ[kr][nt].y);
                    float n0 = tanh_hw(fmaf(r0, dN[kr][nt].x, xiN[kr][nt].x));
                    float n1 = tanh_hw(fmaf(r1, dN[kr][nt].y, xiN[kr][nt].y));
                    float2 nw = make_float2(n0 + z0 * (hold.x - n0),
                                            n1 + z1 * (hold.y - n1));
                    o[li][kr][nt] = nw;
                    *(float2*)&hn[k * 32 + b] = nw;
                }
            }
        }

        // ---- wavefront handshake: release flag, stage next x, per-warp acquire spin ----
        if (t < NT - 1) {
            __syncthreads();                       // all h stores + sH reads of step t done
            if (tid == 0) flag_release(&g_flag[c * 32], t + 1);
            stage_x(t + 1);                        // overlaps the spin below
            if (lane == 0 && c > 0)
                while (flag_acquire(&g_flag[(c - 1) * 32]) <= t) { }
            if (lane == 1 && c < NC - 1)
                while (flag_acquire(&g_flag[(c + 1) * 32]) <= t) { }
            __syncwarp();                          // warp proceeds independently to Phase A
        }
    }

    // ---- fc head (own links; final h in g_h[0] after t=11) ----
    __syncthreads();
    if (tid < 64) {
        int li = tid >> 5, b = tid & 31;
        int l = l0 + li;
        const float* h = g_h[0] + l * 2048;
        float acc = b_fc[l];
#pragma unroll 8
        for (int k = 0; k < NH; k++) acc += __ldcg(&h[k * 32 + b]) * w_fc[l * NH + k];
        out[b * NL + l] = acc;
    }
}

// ---------------- launch ----------------
extern "C" void kernel_launch(void* const* d_in, const int* in_sizes, int n_in,
                              void* d_out, int out_size) {
    const float* x    = (const float*)d_in[0];
    const float* att  = (const float*)d_in[1];
    const float* w_rh = (const float*)d_in[2];
    const float* b_rh = (const float*)d_in[3];
    const float* w_ri = (const float*)d_in[4];
    const float* b_ri = (const float*)d_in[5];
    const float* w_uh = (const float*)d_in[6];
    const float* b_uh = (const float*)d_in[7];
    const float* w_ui = (const float*)d_in[8];
    const float* b_ui = (const float*)d_in[9];
    const float* w_nh = (const float*)d_in[10];
    const float* b_nh = (const float*)d_in[11];
    const float* w_ni = (const float*)d_in[12];
    const float* b_ni = (const float*)d_in[13];
    const float* w_fc = (const float*)d_in[14];
    const float* b_fc = (const float*)d_in[15];

    prep_x<<<6144, 256>>>(x);
    prep_wfrag_h<<<3072, 256>>>(w_rh, w_uh, w_nh);
    prep_wfrag_x<<<3072, 128>>>(w_ri, w_ui, w_ni, b_rh, b_ri, b_uh, b_ui, b_ni);

    fused_kernel<<<NC, 128>>>(att, b_nh, w_fc, b_fc, (float*)d_out);
}